// round 13
// baseline (speedup 1.0000x reference)
#include <cuda_runtime.h>
#include <cuda_bf16.h>
#include <math.h>

// ---------------------------------------------------------------------------
// Problem constants
// ---------------------------------------------------------------------------
#define BB  32
#define PP  512
#define NN  512
#define EMB 256
#define HH  16
#define DD  16

#define KH_LD 24
#define VT_LD 520

// Scratch (device globals -- no allocation allowed)
__device__ __nv_bfloat16 g_Ench[BB * NN * EMB], g_Encl[BB * NN * EMB];
__device__ __nv_bfloat16 g_Lasth[BB * PP * EMB], g_Lastl[BB * PP * EMB];
__device__ __nv_bfloat16 g_Wkh[EMB * EMB], g_Wkl[EMB * EMB];
__device__ __nv_bfloat16 g_Wvh[EMB * EMB], g_Wvl[EMB * EMB];
__device__ __nv_bfloat16 g_Wch[EMB * EMB], g_Wcl[EMB * EMB];
__device__ __nv_bfloat16 g_Wqh[EMB * EMB], g_Wql[EMB * EMB];
__device__ float g_WqX[EMB];
__device__ __nv_bfloat16 g_Kh[BB * HH * NN * KH_LD], g_Kl[BB * HH * NN * KH_LD];
__device__ __nv_bfloat16 g_Vth[BB * HH * DD * VT_LD], g_Vtl[BB * HH * DD * VT_LD];
__device__ __nv_bfloat16 g_Qh[BB * HH * PP * DD], g_Ql[BB * HH * PP * DD];
__device__ __nv_bfloat16 g_atth[BB * PP * EMB], g_attl[BB * PP * EMB];
__device__ __nv_bfloat16 g_mhh[BB * PP * EMB], g_mhl[BB * PP * EMB];
__device__ int g_mask_nz;

// ---------------------------------------------------------------------------
// mma.sync m16n8k16 bf16 + ldmatrix helpers
// ---------------------------------------------------------------------------
__device__ __forceinline__ void mma16816(float* c, const unsigned* a, const unsigned* b) {
    asm volatile(
        "mma.sync.aligned.m16n8k16.row.col.f32.bf16.bf16.f32 "
        "{%0,%1,%2,%3}, {%4,%5,%6,%7}, {%8,%9}, {%0,%1,%2,%3};"
        : "+f"(c[0]), "+f"(c[1]), "+f"(c[2]), "+f"(c[3])
        : "r"(a[0]), "r"(a[1]), "r"(a[2]), "r"(a[3]), "r"(b[0]), "r"(b[1]));
}

__device__ __forceinline__ void ldsm_x4(unsigned& d0, unsigned& d1,
                                        unsigned& d2, unsigned& d3, unsigned addr) {
    asm volatile("ldmatrix.sync.aligned.m8n8.x4.shared.b16 {%0,%1,%2,%3}, [%4];"
                 : "=r"(d0), "=r"(d1), "=r"(d2), "=r"(d3) : "r"(addr));
}

__device__ __forceinline__ unsigned pack_bf16x2(float lo, float hi) {
    unsigned r;
    asm("cvt.rn.satfinite.bf16x2.f32 %0, %1, %2;" : "=r"(r) : "f"(hi), "f"(lo));
    return r;
}

__device__ __forceinline__ void pack_hl(float x0, float x1, unsigned& ph, unsigned& pl) {
    ph = pack_bf16x2(x0, x1);
    const float h0 = __uint_as_float(ph << 16);
    const float h1 = __uint_as_float(ph & 0xFFFF0000u);
    pl = pack_bf16x2(x0 - h0, x1 - h1);
}

__device__ __forceinline__ void cvt_hl(float x, __nv_bfloat16& h, __nv_bfloat16& l) {
    h = __float2bfloat16(x);
    l = __float2bfloat16(x - __bfloat162float(h));
}

#define LDAB 40

// Pipelined GEMM stage layout (elements)
#define P_AH   0
#define P_AL   (128 * LDAB)
#define P_BH   (256 * LDAB)
#define P_BL   (256 * LDAB + 64 * LDAB)
#define P_STAGE (384 * LDAB)

// ---------------------------------------------------------------------------
// Pre-convert kernels: split fp32 inputs to bf16 hi/lo ONCE.
// ---------------------------------------------------------------------------
__global__ void cvt_big_kernel(const float* __restrict__ enc,
                               const float* __restrict__ last)
{
    if (blockIdx.x == 0 && blockIdx.y == 0 && threadIdx.x == 0) g_mask_nz = 0;
    const float4* src = (const float4*)(blockIdx.y ? last : enc);
    uint2* dh = (uint2*)(blockIdx.y ? g_Lasth : g_Ench);
    uint2* dl = (uint2*)(blockIdx.y ? g_Lastl : g_Encl);
#pragma unroll
    for (int it = 0; it < 4; it++) {
        const size_t i = (size_t)blockIdx.x * 1024 + it * 256 + threadIdx.x;
        float4 v = src[i];
        unsigned h01, l01, h23, l23;
        pack_hl(v.x, v.y, h01, l01);
        pack_hl(v.z, v.w, h23, l23);
        dh[i] = make_uint2(h01, h23);
        dl[i] = make_uint2(l01, l23);
    }
}

__global__ void cvt_w_kernel(const float* __restrict__ Wk,
                             const float* __restrict__ Wv,
                             const float* __restrict__ Wc,
                             const float* __restrict__ Wq)
{
    const int z = blockIdx.y;
    const int i = blockIdx.x * 256 + threadIdx.x;  // float4 index, 0..16383
    if (z < 3) {
        const float* src = (z == 0) ? Wk : (z == 1) ? Wv : Wc;
        uint2* dh = (uint2*)((z == 0) ? g_Wkh : (z == 1) ? g_Wvh : g_Wch);
        uint2* dl = (uint2*)((z == 0) ? g_Wkl : (z == 1) ? g_Wvl : g_Wcl);
        float4 v = ((const float4*)src)[i];
        unsigned h01, l01, h23, l23;
        pack_hl(v.x, v.y, h01, l01);
        pack_hl(v.z, v.w, h23, l23);
        dh[i] = make_uint2(h01, h23);
        dl[i] = make_uint2(l01, l23);
    } else {
        const int row = i >> 6, kq = (i & 63) * 4;
        const float* wp = Wq + (size_t)row * 257 + kq;
        unsigned h01, l01, h23, l23;
        pack_hl(wp[0], wp[1], h01, l01);
        pack_hl(wp[2], wp[3], h23, l23);
        ((uint2*)g_Wqh)[i] = make_uint2(h01, h23);
        ((uint2*)g_Wql)[i] = make_uint2(l01, l23);
        if (blockIdx.x == 0) g_WqX[threadIdx.x] = Wq[(size_t)threadIdx.x * 257 + 256];
    }
}

// ---------------------------------------------------------------------------
// Merged projection kernel (pipelined, pure-copy staging).
// ---------------------------------------------------------------------------
__global__ __launch_bounds__(256, 2) void proj_kernel(
    const float* __restrict__ mask)
{
    extern __shared__ __nv_bfloat16 smp[];
    __shared__ unsigned sred[8];

    const int z = blockIdx.z;
    const __nv_bfloat16* Aph = (z == 2) ? g_Lasth : g_Ench;
    const __nv_bfloat16* Apl = (z == 2) ? g_Lastl : g_Encl;
    const __nv_bfloat16* Wph = (z == 0) ? g_Wkh : (z == 1) ? g_Wvh : g_Wqh;
    const __nv_bfloat16* Wpl = (z == 0) ? g_Wkl : (z == 1) ? g_Wvl : g_Wql;
    const bool extra = (z == 2);

    const int m0 = blockIdx.x * 128;
    const int n0 = blockIdx.y * 64;
    const int tid = threadIdx.x;
    const int warp = tid >> 5, lane = tid & 31;
    const int wm = warp >> 1, wn = warp & 1;
    const int gr = lane >> 2, qc = lane & 3;
    const int lt = lane >> 3, lr = lane & 7;

    if (z == 0) {
        unsigned accm = 0;
        const uint4* m4 = (const uint4*)mask + (size_t)blockIdx.y * 128 * 4096
                        + (size_t)blockIdx.x * 4096;
        for (int i = tid; i < 4096; i += 256) {
            uint4 v = m4[i];
            accm |= v.x | v.y | v.z | v.w;
        }
#pragma unroll
        for (int o = 16; o; o >>= 1) accm |= __shfl_xor_sync(0xffffffffu, accm, o);
        if (lane == 0) sred[warp] = accm;
        __syncthreads();
        if (tid == 0) {
            unsigned a = 0;
#pragma unroll
            for (int i = 0; i < 8; i++) a |= sred[i];
            if (a) atomicOr(&g_mask_nz, 1);
        }
    }

    const unsigned sb = (unsigned)__cvta_generic_to_shared(smp);
    const unsigned aH0 = sb + (P_AH + (wm * 32 + (lt & 1) * 8 + lr) * LDAB + (lt >> 1) * 8) * 2;
    const unsigned aL0 = sb + (P_AL + (wm * 32 + (lt & 1) * 8 + lr) * LDAB + (lt >> 1) * 8) * 2;
    const unsigned bH0 = sb + (P_BH + (wn * 32 + (lt >> 1) * 8 + lr) * LDAB + (lt & 1) * 8) * 2;
    const unsigned bL0 = sb + (P_BL + (wn * 32 + (lt >> 1) * 8 + lr) * LDAB + (lt & 1) * 8) * 2;

    float acc[2][4][4];
#pragma unroll
    for (int mt = 0; mt < 2; mt++)
#pragma unroll
        for (int nt = 0; nt < 4; nt++)
#pragma unroll
            for (int e = 0; e < 4; e++) acc[mt][nt][e] = 0.0f;

    // copy indices: A 2 uint4/thread/buffer, B 1 uint4/thread/buffer
    const int arow0 = tid >> 2,        ac80 = tid & 3;          // lin = tid
    const int arow1 = (tid + 256) >> 2, ac81 = (tid + 256) & 3;  // lin = tid+256
    const int brow = tid >> 2, bc8 = tid & 3;

    uint4 avh[2], avl[2], wvh, wvl;
    {
        const size_t sA0 = (size_t)(m0 + arow0) * 32 + ac80;
        const size_t sA1 = (size_t)(m0 + arow1) * 32 + ac81;
        avh[0] = ((const uint4*)Aph)[sA0]; avl[0] = ((const uint4*)Apl)[sA0];
        avh[1] = ((const uint4*)Aph)[sA1]; avl[1] = ((const uint4*)Apl)[sA1];
        const size_t sB = (size_t)(n0 + brow) * 32 + bc8;
        wvh = ((const uint4*)Wph)[sB]; wvl = ((const uint4*)Wpl)[sB];
    }

#pragma unroll 1
    for (int kb = 0; kb < 8; kb++) {
        const int bufo = (kb & 1) * P_STAGE;
        __nv_bfloat16* Ah = smp + bufo + P_AH;
        __nv_bfloat16* Al = smp + bufo + P_AL;
        __nv_bfloat16* Bh = smp + bufo + P_BH;
        __nv_bfloat16* Bl = smp + bufo + P_BL;
        *(uint4*)&Ah[arow0 * LDAB + ac80 * 8] = avh[0];
        *(uint4*)&Al[arow0 * LDAB + ac80 * 8] = avl[0];
        *(uint4*)&Ah[arow1 * LDAB + ac81 * 8] = avh[1];
        *(uint4*)&Al[arow1 * LDAB + ac81 * 8] = avl[1];
        *(uint4*)&Bh[brow * LDAB + bc8 * 8] = wvh;
        *(uint4*)&Bl[brow * LDAB + bc8 * 8] = wvl;
        __syncthreads();

        if (kb < 7) {
            const int k8 = ((kb + 1) * 32) >> 3;
            const size_t sA0 = (size_t)(m0 + arow0) * 32 + k8 + ac80;
            const size_t sA1 = (size_t)(m0 + arow1) * 32 + k8 + ac81;
            avh[0] = ((const uint4*)Aph)[sA0]; avl[0] = ((const uint4*)Apl)[sA0];
            avh[1] = ((const uint4*)Aph)[sA1]; avl[1] = ((const uint4*)Apl)[sA1];
            const size_t sB = (size_t)(n0 + brow) * 32 + k8 + bc8;
            wvh = ((const uint4*)Wph)[sB]; wvl = ((const uint4*)Wpl)[sB];
        }

        const unsigned bo2 = bufo * 2;
#pragma unroll
        for (int ks = 0; ks < 32; ks += 16) {
            unsigned ah[2][4], al[2][4], bh[4][2], bl[4][2];
#pragma unroll
            for (int mt = 0; mt < 2; mt++) {
                ldsm_x4(ah[mt][0], ah[mt][1], ah[mt][2], ah[mt][3],
                        aH0 + bo2 + (mt * 16 * LDAB + ks) * 2);
                ldsm_x4(al[mt][0], al[mt][1], al[mt][2], al[mt][3],
                        aL0 + bo2 + (mt * 16 * LDAB + ks) * 2);
            }
#pragma unroll
            for (int p = 0; p < 2; p++) {
                ldsm_x4(bh[2 * p][0], bh[2 * p][1], bh[2 * p + 1][0], bh[2 * p + 1][1],
                        bH0 + bo2 + (p * 16 * LDAB + ks) * 2);
                ldsm_x4(bl[2 * p][0], bl[2 * p][1], bl[2 * p + 1][0], bl[2 * p + 1][1],
                        bL0 + bo2 + (p * 16 * LDAB + ks) * 2);
            }
#pragma unroll
            for (int mt = 0; mt < 2; mt++)
#pragma unroll
                for (int nt = 0; nt < 4; nt++) {
                    mma16816(acc[mt][nt], ah[mt], bh[nt]);
                    mma16816(acc[mt][nt], ah[mt], bl[nt]);
                    mma16816(acc[mt][nt], al[mt], bh[nt]);
                }
        }
    }

    // ---- epilogue: write bf16 hi/lo in attention-ready layouts ----
    const float* loadv = nullptr;  // set via param below
    // (loadv handled by caller-passed pointer in launch wrapper; see param)
    // NOTE: replaced by g_WqX + load passed as kernel arg.
#pragma unroll
    for (int mt = 0; mt < 2; mt++) {
#pragma unroll
        for (int part = 0; part < 2; part++) {
            const int m = m0 + wm * 32 + mt * 16 + gr + part * 8;
            const int b = m >> 9, n = m & 511;
#pragma unroll
            for (int nt = 0; nt < 4; nt++) {
                const int col = n0 + wn * 32 + nt * 8 + 2 * qc;
                float2 v = make_float2(acc[mt][nt][part * 2], acc[mt][nt][part * 2 + 1]);
                const int h = col >> 4, d = col & 15;
                const size_t bh = (size_t)(b * 16 + h);
                if (z == 0) {
                    unsigned ph, pl;
                    pack_hl(v.x, v.y, ph, pl);
                    *(unsigned*)&g_Kh[(bh * 512 + n) * KH_LD + d] = ph;
                    *(unsigned*)&g_Kl[(bh * 512 + n) * KH_LD + d] = pl;
                } else if (z == 1) {
                    __nv_bfloat16 hx, lx, hy, ly;
                    cvt_hl(v.x, hx, lx);
                    cvt_hl(v.y, hy, ly);
                    g_Vth[(bh * 16 + d) * VT_LD + n]     = hx;
                    g_Vtl[(bh * 16 + d) * VT_LD + n]     = lx;
                    g_Vth[(bh * 16 + d + 1) * VT_LD + n] = hy;
                    g_Vtl[(bh * 16 + d + 1) * VT_LD + n] = ly;
                }
            }
        }
    }
    (void)loadv;
}

// Separate tiny epilogue path for z==2 handled inside proj via template would
// bloat; instead proj_q variant:
__global__ __launch_bounds__(256, 2) void proj_q_epilogue_dummy() {}

// ---------------------------------------------------------------------------
// Q projection epilogue needs `load`; simplest: proj handles z<2 only and a
// second kernel instantiation handles z==2. To keep one kernel, we pass load:
// ---------------------------------------------------------------------------
__global__ __launch_bounds__(256, 2) void proj_q_kernel(
    const float* __restrict__ loadv)
{
    extern __shared__ __nv_bfloat16 smp[];
    const __nv_bfloat16* Aph = g_Lasth;
    const __nv_bfloat16* Apl = g_Lastl;
    const __nv_bfloat16* Wph = g_Wqh;
    const __nv_bfloat16* Wpl = g_Wql;

    const int m0 = blockIdx.x * 128;
    const int n0 = blockIdx.y * 64;
    const int tid = threadIdx.x;
    const int warp = tid >> 5, lane = tid & 31;
    const int wm = warp >> 1, wn = warp & 1;
    const int gr = lane >> 2, qc = lane & 3;
    const int lt = lane >> 3, lr = lane & 7;

    const unsigned sb = (unsigned)__cvta_generic_to_shared(smp);
    const unsigned aH0 = sb + (P_AH + (wm * 32 + (lt & 1) * 8 + lr) * LDAB + (lt >> 1) * 8) * 2;
    const unsigned aL0 = sb + (P_AL + (wm * 32 + (lt & 1) * 8 + lr) * LDAB + (lt >> 1) * 8) * 2;
    const unsigned bH0 = sb + (P_BH + (wn * 32 + (lt >> 1) * 8 + lr) * LDAB + (lt & 1) * 8) * 2;
    const unsigned bL0 = sb + (P_BL + (wn * 32 + (lt >> 1) * 8 + lr) * LDAB + (lt & 1) * 8) * 2;

    float acc[2][4][4];
#pragma unroll
    for (int mt = 0; mt < 2; mt++)
#pragma unroll
        for (int nt = 0; nt < 4; nt++)
#pragma unroll
            for (int e = 0; e < 4; e++) acc[mt][nt][e] = 0.0f;

    const int arow0 = tid >> 2,        ac80 = tid & 3;
    const int arow1 = (tid + 256) >> 2, ac81 = (tid + 256) & 3;
    const int brow = tid >> 2, bc8 = tid & 3;

    uint4 avh[2], avl[2], wvh, wvl;
    {
        const size_t sA0 = (size_t)(m0 + arow0) * 32 + ac80;
        const size_t sA1 = (size_t)(m0 + arow1) * 32 + ac81;
        avh[0] = ((const uint4*)Aph)[sA0]; avl[0] = ((const uint4*)Apl)[sA0];
        avh[1] = ((const uint4*)Aph)[sA1]; avl[1] = ((const uint4*)Apl)[sA1];
        const size_t sB = (size_t)(n0 + brow) * 32 + bc8;
        wvh = ((const uint4*)Wph)[sB]; wvl = ((const uint4*)Wpl)[sB];
    }

#pragma unroll 1
    for (int kb = 0; kb < 8; kb++) {
        const int bufo = (kb & 1) * P_STAGE;
        __nv_bfloat16* Ah = smp + bufo + P_AH;
        __nv_bfloat16* Al = smp + bufo + P_AL;
        __nv_bfloat16* Bh = smp + bufo + P_BH;
        __nv_bfloat16* Bl = smp + bufo + P_BL;
        *(uint4*)&Ah[arow0 * LDAB + ac80 * 8] = avh[0];
        *(uint4*)&Al[arow0 * LDAB + ac80 * 8] = avl[0];
        *(uint4*)&Ah[arow1 * LDAB + ac81 * 8] = avh[1];
        *(uint4*)&Al[arow1 * LDAB + ac81 * 8] = avl[1];
        *(uint4*)&Bh[brow * LDAB + bc8 * 8] = wvh;
        *(uint4*)&Bl[brow * LDAB + bc8 * 8] = wvl;
        __syncthreads();

        if (kb < 7) {
            const int k8 = ((kb + 1) * 32) >> 3;
            const size_t sA0 = (size_t)(m0 + arow0) * 32 + k8 + ac80;
            const size_t sA1 = (size_t)(m0 + arow1) * 32 + k8 + ac81;
            avh[0] = ((const uint4*)Aph)[sA0]; avl[0] = ((const uint4*)Apl)[sA0];
            avh[1] = ((const uint4*)Aph)[sA1]; avl[1] = ((const uint4*)Apl)[sA1];
            const size_t sB = (size_t)(n0 + brow) * 32 + k8 + bc8;
            wvh = ((const uint4*)Wph)[sB]; wvl = ((const uint4*)Wpl)[sB];
        }

        const unsigned bo2 = bufo * 2;
#pragma unroll
        for (int ks = 0; ks < 32; ks += 16) {
            unsigned ah[2][4], al[2][4], bh[4][2], bl[4][2];
#pragma unroll
            for (int mt = 0; mt < 2; mt++) {
                ldsm_x4(ah[mt][0], ah[mt][1], ah[mt][2], ah[mt][3],
                        aH0 + bo2 + (mt * 16 * LDAB + ks) * 2);
                ldsm_x4(al[mt][0], al[mt][1], al[mt][2], al[mt][3],
                        aL0 + bo2 + (mt * 16 * LDAB + ks) * 2);
            }
#pragma unroll
            for (int p = 0; p < 2; p++) {
                ldsm_x4(bh[2 * p][0], bh[2 * p][1], bh[2 * p + 1][0], bh[2 * p + 1][1],
                        bH0 + bo2 + (p * 16 * LDAB + ks) * 2);
                ldsm_x4(bl[2 * p][0], bl[2 * p][1], bl[2 * p + 1][0], bl[2 * p + 1][1],
                        bL0 + bo2 + (p * 16 * LDAB + ks) * 2);
            }
#pragma unroll
            for (int mt = 0; mt < 2; mt++)
#pragma unroll
                for (int nt = 0; nt < 4; nt++) {
                    mma16816(acc[mt][nt], ah[mt], bh[nt]);
                    mma16816(acc[mt][nt], ah[mt], bl[nt]);
                    mma16816(acc[mt][nt], al[mt], bh[nt]);
                }
        }
    }

#pragma unroll
    for (int mt = 0; mt < 2; mt++) {
#pragma unroll
        for (int part = 0; part < 2; part++) {
            const int m = m0 + wm * 32 + mt * 16 + gr + part * 8;
            const int b = m >> 9, n = m & 511;
            const float ex = loadv[m];
#pragma unroll
            for (int nt = 0; nt < 4; nt++) {
                const int col = n0 + wn * 32 + nt * 8 + 2 * qc;
                float2 v = make_float2(acc[mt][nt][part * 2], acc[mt][nt][part * 2 + 1]);
                v.x += ex * g_WqX[col];
                v.y += ex * g_WqX[col + 1];
                v.x *= 0.25f; v.y *= 0.25f;
                const int h = col >> 4, d = col & 15;
                const size_t bh = (size_t)(b * 16 + h);
                unsigned ph, pl;
                pack_hl(v.x, v.y, ph, pl);
                *(unsigned*)&g_Qh[(bh * 512 + n) * 16 + d] = ph;
                *(unsigned*)&g_Ql[(bh * 512 + n) * 16 + d] = pl;
            }
        }
    }
}

// ---------------------------------------------------------------------------
// Wc projection (pipelined, pure-copy staging): att @ Wc^T + bias -> mh (hi/lo)
// ---------------------------------------------------------------------------
__global__ __launch_bounds__(256, 2) void gemm_wc_kernel(
    const float* __restrict__ bias)
{
    extern __shared__ __nv_bfloat16 smp[];

    const int m0 = blockIdx.x * 128;
    const int n0 = blockIdx.y * 64;
    const int tid = threadIdx.x;
    const int warp = tid >> 5, lane = tid & 31;
    const int wm = warp >> 1, wn = warp & 1;
    const int gr = lane >> 2, qc = lane & 3;
    const int lt = lane >> 3, lr = lane & 7;

    const unsigned sb = (unsigned)__cvta_generic_to_shared(smp);
    const unsigned aH0 = sb + (P_AH + (wm * 32 + (lt & 1) * 8 + lr) * LDAB + (lt >> 1) * 8) * 2;
    const unsigned aL0 = sb + (P_AL + (wm * 32 + (lt & 1) * 8 + lr) * LDAB + (lt >> 1) * 8) * 2;
    const unsigned bH0 = sb + (P_BH + (wn * 32 + (lt >> 1) * 8 + lr) * LDAB + (lt & 1) * 8) * 2;
    const unsigned bL0 = sb + (P_BL + (wn * 32 + (lt >> 1) * 8 + lr) * LDAB + (lt & 1) * 8) * 2;

    float acc[2][4][4];
#pragma unroll
    for (int mt = 0; mt < 2; mt++)
#pragma unroll
        for (int nt = 0; nt < 4; nt++)
#pragma unroll
            for (int e = 0; e < 4; e++) acc[mt][nt][e] = 0.0f;

    const int arow0 = tid >> 2,        ac80 = tid & 3;
    const int arow1 = (tid + 256) >> 2, ac81 = (tid + 256) & 3;
    const int brow = tid >> 2, bc8 = tid & 3;

    uint4 avh[2], avl[2], wvh, wvl;
    {
        const size_t sA0 = (size_t)(m0 + arow0) * 32 + ac80;
        const size_t sA1 = (size_t)(m0 + arow1) * 32 + ac81;
        avh[0] = ((const uint4*)g_atth)[sA0]; avl[0] = ((const uint4*)g_attl)[sA0];
        avh[1] = ((const uint4*)g_atth)[sA1]; avl[1] = ((const uint4*)g_attl)[sA1];
        const size_t sB = (size_t)(n0 + brow) * 32 + bc8;
        wvh = ((const uint4*)g_Wch)[sB]; wvl = ((const uint4*)g_Wcl)[sB];
    }

#pragma unroll 1
    for (int kb = 0; kb < 8; kb++) {
        const int bufo = (kb & 1) * P_STAGE;
        __nv_bfloat16* Ah = smp + bufo + P_AH;
        __nv_bfloat16* Al = smp + bufo + P_AL;
        __nv_bfloat16* Bh = smp + bufo + P_BH;
        __nv_bfloat16* Bl = smp + bufo + P_BL;
        *(uint4*)&Ah[arow0 * LDAB + ac80 * 8] = avh[0];
        *(uint4*)&Al[arow0 * LDAB + ac80 * 8] = avl[0];
        *(uint4*)&Ah[arow1 * LDAB + ac81 * 8] = avh[1];
        *(uint4*)&Al[arow1 * LDAB + ac81 * 8] = avl[1];
        *(uint4*)&Bh[brow * LDAB + bc8 * 8] = wvh;
        *(uint4*)&Bl[brow * LDAB + bc8 * 8] = wvl;
        __syncthreads();

        if (kb < 7) {
            const int k8 = ((kb + 1) * 32) >> 3;
            const size_t sA0 = (size_t)(m0 + arow0) * 32 + k8 + ac80;
            const size_t sA1 = (size_t)(m0 + arow1) * 32 + k8 + ac81;
            avh[0] = ((const uint4*)g_atth)[sA0]; avl[0] = ((const uint4*)g_attl)[sA0];
            avh[1] = ((const uint4*)g_atth)[sA1]; avl[1] = ((const uint4*)g_attl)[sA1];
            const size_t sB = (size_t)(n0 + brow) * 32 + k8 + bc8;
            wvh = ((const uint4*)g_Wch)[sB]; wvl = ((const uint4*)g_Wcl)[sB];
        }

        const unsigned bo2 = bufo * 2;
#pragma unroll
        for (int ks = 0; ks < 32; ks += 16) {
            unsigned ah[2][4], al[2][4], bh[4][2], bl[4][2];
#pragma unroll
            for (int mt = 0; mt < 2; mt++) {
                ldsm_x4(ah[mt][0], ah[mt][1], ah[mt][2], ah[mt][3],
                        aH0 + bo2 + (mt * 16 * LDAB + ks) * 2);
                ldsm_x4(al[mt][0], al[mt][1], al[mt][2], al[mt][3],
                        aL0 + bo2 + (mt * 16 * LDAB + ks) * 2);
            }
#pragma unroll
            for (int p = 0; p < 2; p++) {
                ldsm_x4(bh[2 * p][0], bh[2 * p][1], bh[2 * p + 1][0], bh[2 * p + 1][1],
                        bH0 + bo2 + (p * 16 * LDAB + ks) * 2);
                ldsm_x4(bl[2 * p][0], bl[2 * p][1], bl[2 * p + 1][0], bl[2 * p + 1][1],
                        bL0 + bo2 + (p * 16 * LDAB + ks) * 2);
            }
#pragma unroll
            for (int mt = 0; mt < 2; mt++)
#pragma unroll
                for (int nt = 0; nt < 4; nt++) {
                    mma16816(acc[mt][nt], ah[mt], bh[nt]);
                    mma16816(acc[mt][nt], ah[mt], bl[nt]);
                    mma16816(acc[mt][nt], al[mt], bh[nt]);
                }
        }
    }

#pragma unroll
    for (int mt = 0; mt < 2; mt++) {
#pragma unroll
        for (int part = 0; part < 2; part++) {
            const int m = m0 + wm * 32 + mt * 16 + gr + part * 8;
#pragma unroll
            for (int nt = 0; nt < 4; nt++) {
                const int col = n0 + wn * 32 + nt * 8 + 2 * qc;
                float2 v = make_float2(acc[mt][nt][part * 2], acc[mt][nt][part * 2 + 1]);
                v.x += bias[col]; v.y += bias[col + 1];
                unsigned ph, pl;
                pack_hl(v.x, v.y, ph, pl);
                *(unsigned*)&g_mhh[(size_t)m * 256 + col] = ph;
                *(unsigned*)&g_mhl[(size_t)m * 256 + col] = pl;
            }
        }
    }
}

// ---------------------------------------------------------------------------
// Flash attention v9 (copies) -- epilogue now writes att as hi/lo.
// ---------------------------------------------------------------------------
#define A6_KH   0
#define A6_KL   (512 * KH_LD)
#define A6_VTH  (2 * 512 * KH_LD)
#define A6_VTL  (A6_VTH + 16 * VT_LD)
#define A6_QH   (A6_VTL + 16 * VT_LD)
#define A6_QL   (A6_QH + 128 * 16)
#define A6_TOT  (A6_QL + 128 * 16)

__global__ __launch_bounds__(256, 2) void attention9_kernel(
    const float* __restrict__ mask)
{
    extern __shared__ __nv_bfloat16 smb[];

    const int bh = blockIdx.x;
    const int b  = bh >> 4;
    const int h  = bh & 15;
    const int tid = threadIdx.x;
    const int anymask = g_mask_nz;

    {
        const uint4* s1 = (const uint4*)g_Kh + (size_t)bh * 1536;
        const uint4* s2 = (const uint4*)g_Kl + (size_t)bh * 1536;
        uint4* d1 = (uint4*)(smb + A6_KH);
        uint4* d2 = (uint4*)(smb + A6_KL);
        for (int i = tid; i < 1536; i += 256) { d1[i] = s1[i]; d2[i] = s2[i]; }
        const uint4* s3 = (const uint4*)g_Vth + (size_t)bh * 1040;
        const uint4* s4 = (const uint4*)g_Vtl + (size_t)bh * 1040;
        uint4* d3 = (uint4*)(smb + A6_VTH);
        uint4* d4 = (uint4*)(smb + A6_VTL);
        for (int i = tid; i < 1040; i += 256) { d3[i] = s3[i]; d4[i] = s4[i]; }
    }

    const int warp = tid >> 5, lane = tid & 31;
    const int gr = lane >> 2, qc = lane & 3;
    const int lt = lane >> 3, lr = lane & 7;
    const int prow = warp * 16;

    const unsigned sb = (unsigned)__cvta_generic_to_shared(smb);
    const unsigned kBase = sb + ((lt < 2 ? A6_KH : A6_KL)
                                 + lr * KH_LD + (lt & 1) * 8) * 2;
    const unsigned vBase = sb + ((lt < 2 ? A6_VTH : A6_VTL)
                                 + lr * VT_LD + (lt & 1) * 8) * 2;

#pragma unroll 1
    for (int ip = 0; ip < 2; ip++) {
        const int p0 = blockIdx.y * 256 + ip * 128;

        __syncthreads();
        {
            const uint4* qs = (const uint4*)g_Qh + ((size_t)bh * 512 + p0) * 2;
            const uint4* ql = (const uint4*)g_Ql + ((size_t)bh * 512 + p0) * 2;
            uint4* qdh = (uint4*)(smb + A6_QH);
            uint4* qdl = (uint4*)(smb + A6_QL);
            qdh[tid] = qs[tid];
            qdl[tid] = ql[tid];
        }
        __syncthreads();

        __nv_bfloat16* Qh = smb + A6_QH;
        __nv_bfloat16* Ql = smb + A6_QL;
        unsigned qh[4], ql[4];
        {
            const int base = (prow + gr) * 16 + 2 * qc;
            qh[0] = *(const unsigned*)&Qh[base];
            qh[1] = *(const unsigned*)&Qh[base + 8 * 16];
            qh[2] = *(const unsigned*)&Qh[base + 8];
            qh[3] = *(const unsigned*)&Qh[base + 8 * 16 + 8];
            ql[0] = *(const unsigned*)&Ql[base];
            ql[1] = *(const unsigned*)&Ql[base + 8 * 16];
            ql[2] = *(const unsigned*)&Ql[base + 8];
            ql[3] = *(const unsigned*)&Ql[base + 8 * 16 + 8];
        }

        float m0 = -1e30f, m1 = -1e30f, l0 = 0.0f, l1 = 0.0f;
        float O[2][4];
#pragma unroll
        for (int nd = 0; nd < 2; nd++)
#pragma unroll
            for (int e = 0; e < 4; e++) O[nd][e] = 0.0f;

        const size_t mrow0 = ((size_t)(b * PP + p0 + prow + gr)) * NN;
        const size_t mrow1 = ((size_t)(b * PP + p0 + prow + gr + 8)) * NN;

#pragma unroll 1
        for (int c = 0; c < 8; c++) {
            const int n0c = c * 64;

            float s[8][4];
#pragma unroll
            for (int nf = 0; nf < 8; nf++) {
                s[nf][0] = s[nf][1] = s[nf][2] = s[nf][3] = 0.0f;
                unsigned kbh[2], kbl[2];
                ldsm_x4(kbh[0], kbh[1], kbl[0], kbl[1],
                        kBase + (n0c + nf * 8) * (KH_LD * 2));
                mma16816(s[nf], qh, kbh);
                mma16816(s[nf], qh, kbl);
                mma16816(s[nf], ql, kbh);
            }

            if (anymask) {
#pragma unroll
                for (int nf = 0; nf < 8; nf++) {
                    const int ncol = n0c + nf * 8 + 2 * qc;
                    float2 mk0 = *(const float2*)&mask[mrow0 + ncol];
                    float2 mk1 = *(const float2*)&mask[mrow1 + ncol];
                    s[nf][0] += mk0.x; s[nf][1] += mk0.y;
                    s[nf][2] += mk1.x; s[nf][3] += mk1.y;
                }
            }

            float mx0 = -1e30f, mx1 = -1e30f;
#pragma unroll
            for (int nf = 0; nf < 8; nf++) {
                mx0 = fmaxf(mx0, fmaxf(s[nf][0], s[nf][1]));
                mx1 = fmaxf(mx1, fmaxf(s[nf][2], s[nf][3]));
            }
            mx0 = fmaxf(mx0, __shfl_xor_sync(0xffffffffu, mx0, 1));
            mx0 = fmaxf(mx0, __shfl_xor_sync(0xffffffffu, mx0, 2));
            mx1 = fmaxf(mx1, __shfl_xor_sync(0xffffffffu, mx1, 1));
            mx1 = fmaxf(mx1, __shfl_xor_sync(0xffffffffu, mx1, 2));

            const float mn0 = fmaxf(m0, mx0);
            const float mn1 = fmaxf(m1, mx1);
            const float f0 = __expf(m0 - mn0);
            const float f1 = __expf(m1 - mn1);
            m0 = mn0; m1 = mn1;
#pragma unroll
            for (int nd = 0; nd < 2; nd++) {
                O[nd][0] *= f0; O[nd][1] *= f0;
                O[nd][2] *= f1; O[nd][3] *= f1;
            }

            float rs0 = 0.0f, rs1 = 0.0f;
#pragma unroll
            for (int nf = 0; nf < 8; nf++) {
                s[nf][0] = __expf(s[nf][0] - mn0);
                s[nf][1] = __expf(s[nf][1] - mn0);
                s[nf][2] = __expf(s[nf][2] - mn1);
                s[nf][3] = __expf(s[nf][3] - mn1);
                rs0 += s[nf][0] + s[nf][1];
                rs1 += s[nf][2] + s[nf][3];
            }
            rs0 += __shfl_xor_sync(0xffffffffu, rs0, 1);
            rs0 += __shfl_xor_sync(0xffffffffu, rs0, 2);
            rs1 += __shfl_xor_sync(0xffffffffu, rs1, 1);
            rs1 += __shfl_xor_sync(0xffffffffu, rs1, 2);
            l0 = l0 * f0 + rs0;
            l1 = l1 * f1 + rs1;

#pragma unroll
            for (int t = 0; t < 4; t++) {
                unsigned ah[4], al[4];
                pack_hl(s[2 * t][0],     s[2 * t][1],     ah[0], al[0]);
                pack_hl(s[2 * t][2],     s[2 * t][3],     ah[1], al[1]);
                pack_hl(s[2 * t + 1][0], s[2 * t + 1][1], ah[2], al[2]);
                pack_hl(s[2 * t + 1][2], s[2 * t + 1][3], ah[3], al[3]);
#pragma unroll
                for (int nd = 0; nd < 2; nd++) {
                    unsigned vbh[2], vbl[2];
                    ldsm_x4(vbh[0], vbh[1], vbl[0], vbl[1],
                            vBase + (nd * 8 * VT_LD + n0c + 16 * t) * 2);
                    mma16816(O[nd], ah, vbh);
                    mma16816(O[nd], ah, vbl);
                    mma16816(O[nd], al, vbh);
                }
            }
        }

        const float inv0 = 1.0f / l0;
        const float inv1 = 1.0f / l1;
        const size_t r0 = (size_t)(b * PP + p0 + prow + gr) * 256 + h * 16;
        const size_t r1 = (size_t)(b * PP + p0 + prow + gr + 8) * 256 + h * 16;
#pragma unroll
        for (int nd = 0; nd < 2; nd++) {
            unsigned ph, pl;
            pack_hl(O[nd][0] * inv0, O[nd][1] * inv0, ph, pl);
            *(unsigned*)&g_atth[r0 + nd * 8 + 2 * qc] = ph;
            *(unsigned*)&g_attl[r0 + nd * 8 + 2 * qc] = pl;
            pack_hl(O[nd][2] * inv1, O[nd][3] * inv1, ph, pl);
            *(unsigned*)&g_atth[r1 + nd * 8 + 2 * qc] = ph;
            *(unsigned*)&g_attl[r1 + nd * 8 + 2 * qc] = pl;
        }
    }
}

// ---------------------------------------------------------------------------
// Final fused kernel v8: pure-copy staging (mh + enc pre-split).
// ---------------------------------------------------------------------------
#define F_BH 0
#define F_BL (128 * LDAB)
#define F_BSTAGE (256 * LDAB)
#define F_AH (2 * F_BSTAGE)
#define F_A_LD 264
#define F_AL (F_AH + 32 * F_A_LD)
#define F_TOT (F_AL + 32 * F_A_LD)

__global__ __launch_bounds__(256, 2) void final8_kernel(
    const float* __restrict__ dist,
    const float* __restrict__ mask,
    float* __restrict__ out)
{
    extern __shared__ __nv_bfloat16 smf[];
    __shared__ float s_tau[32];
    __shared__ float s_sum[32];

    const int b = blockIdx.y;
    const int p0 = blockIdx.x * 32;
    const int tid = threadIdx.x;
    const int warp = tid >> 5, lane = tid & 31;
    const int wm = warp >> 2, wn = warp & 3;
    const int gr = lane >> 2, qc = lane & 3;
    const int lt = lane >> 3, lr = lane & 7;
    const int anymask = g_mask_nz;

    if (tid < 32) s_sum[tid] = 0.0f;

#pragma unroll 1
    for (int rr = 0; rr < 4; rr++) {
        const int r = warp * 4 + rr;
        const float* drow = dist + ((size_t)(b * PP + p0 + r)) * NN;
        unsigned key[16];
#pragma unroll
        for (int j = 0; j < 16; j++) {
            unsigned u = __float_as_uint(drow[j * 32 + lane]);
            key[j] = (u & 0x80000000u) ? ~u : (u ^ 0x80000000u);
        }
        unsigned lo = 0u, hi = 0xffffffffu;
#pragma unroll 1
        for (int it = 0; it < 32; it++) {
            const unsigned mid = lo + ((hi - lo) >> 1);
            int c = 0;
#pragma unroll
            for (int j = 0; j < 16; j++) c += (key[j] <= mid) ? 1 : 0;
            c = __reduce_add_sync(0xffffffffu, c);
            if (c >= 100) hi = mid; else lo = mid + 1;
        }
        if (lane == 0) {
            const unsigned tau = hi;
            const unsigned u = (tau & 0x80000000u) ? (tau ^ 0x80000000u) : ~tau;
            s_tau[r] = __uint_as_float(u);
        }
    }

    // ---- stage A (mh tile, FULL K) once via copies ----
    __nv_bfloat16* Ah = smf + F_AH;
    __nv_bfloat16* Al = smf + F_AL;
#pragma unroll
    for (int i = 0; i < 4; i++) {
        const int lin = tid + i * 256;
        const int row = lin >> 5, c8 = lin & 31;
        const size_t src = (size_t)(b * PP + p0 + row) * 32 + c8;
        *(uint4*)&Ah[row * F_A_LD + c8 * 8] = ((const uint4*)g_mhh)[src];
        *(uint4*)&Al[row * F_A_LD + c8 * 8] = ((const uint4*)g_mhl)[src];
    }
    __syncthreads();

    const unsigned sb = (unsigned)__cvta_generic_to_shared(smf);
    const unsigned aHb = sb + (F_AH + (wm * 16 + (lt & 1) * 8 + lr) * F_A_LD + (lt >> 1) * 8) * 2;
    const unsigned aLb = sb + (F_AL + (wm * 16 + (lt & 1) * 8 + lr) * F_A_LD + (lt >> 1) * 8) * 2;
    const unsigned bHb = sb + (F_BH + (wn * 32 + (lt >> 1) * 8 + lr) * LDAB + (lt & 1) * 8) * 2;
    const unsigned bLb = sb + (F_BL + (wn * 32 + (lt >> 1) * 8 + lr) * LDAB + (lt & 1) * 8) * 2;

    const size_t outbase = ((size_t)(b * PP + p0)) * NN;
    const int brow0 = tid >> 2,        bc80 = tid & 3;
    const int brow1 = (tid + 256) >> 2, bc81 = (tid + 256) & 3;

#pragma unroll 1
    for (int nc = 0; nc < 4; nc++) {
        float acc[4][4];
#pragma unroll
        for (int nt = 0; nt < 4; nt++)
#pragma unroll
            for (int e = 0; e < 4; e++) acc[nt][e] = 0.0f;

        uint4 bvh[2], bvl[2];
        {
            const size_t s0 = (size_t)(b * NN + nc * 128 + brow0) * 32 + bc80;
            const size_t s1 = (size_t)(b * NN + nc * 128 + brow1) * 32 + bc81;
            bvh[0] = ((const uint4*)g_Ench)[s0]; bvl[0] = ((const uint4*)g_Encl)[s0];
            bvh[1] = ((const uint4*)g_Ench)[s1]; bvl[1] = ((const uint4*)g_Encl)[s1];
        }

#pragma unroll 1
        for (int kb = 0; kb < 8; kb++) {
            const int bufo = (kb & 1) * F_BSTAGE;
            __nv_bfloat16* Bh = smf + bufo + F_BH;
            __nv_bfloat16* Bl = smf + bufo + F_BL;
            *(uint4*)&Bh[brow0 * LDAB + bc80 * 8] = bvh[0];
            *(uint4*)&Bl[brow0 * LDAB + bc80 * 8] = bvl[0];
            *(uint4*)&Bh[brow1 * LDAB + bc81 * 8] = bvh[1];
            *(uint4*)&Bl[brow1 * LDAB + bc81 * 8] = bvl[1];
            __syncthreads();

            if (kb < 7) {
                const int k8 = ((kb + 1) * 32) >> 3;
                const size_t s0 = (size_t)(b * NN + nc * 128 + brow0) * 32 + k8 + bc80;
                const size_t s1 = (size_t)(b * NN + nc * 128 + brow1) * 32 + k8 + bc81;
                bvh[0] = ((const uint4*)g_Ench)[s0]; bvl[0] = ((const uint4*)g_Encl)[s0];
                bvh[1] = ((const uint4*)g_Ench)[s1]; bvl[1] = ((const uint4*)g_Encl)[s1];
            }

            const unsigned bo2 = bufo * 2;
#pragma unroll
            for (int ks = 0; ks < 32; ks += 16) {
                const int ka = kb * 32 + ks;
                unsigned ah[4], al[4], bh[4][2], bl[4][2];
                ldsm_x4(ah[0], ah[1], ah[2], ah[3], aHb + ka * 2);
                ldsm_x4(al[0], al[1], al[2], al[3], aLb + ka * 2);
#pragma unroll
                for (int p = 0; p < 2; p++) {
                    ldsm_x4(bh[2 * p][0], bh[2 * p][1], bh[2 * p + 1][0], bh[2 * p + 1][1],
                            bHb + bo2 + (p * 16 * LDAB + ks) * 2);
                    ldsm_x4(bl[2 * p][0], bl[2 * p][1], bl[2 * p + 1][0], bl[2 * p + 1][1],
                            bLb + bo2 + (p * 16 * LDAB + ks) * 2);
                }
#pragma unroll
                for (int nt = 0; nt < 4; nt++) {
                    mma16816(acc[nt], ah, bh[nt]);
                    mma16816(acc[nt], ah, bl[nt]);
                    mma16816(acc[nt], al, bh[nt]);
                }
            }
        }

#pragma unroll
        for (int part = 0; part < 2; part++) {
            const int rloc = wm * 16 + gr + part * 8;
            const float tauf = s_tau[rloc];
            const size_t rowoff = outbase + (size_t)rloc * NN;
            float lsum = 0.0f;
#pragma unroll
            for (int nt = 0; nt < 4; nt++) {
                const int col = nc * 128 + wn * 32 + nt * 8 + 2 * qc;
                float2 d2 = *(const float2*)&dist[rowoff + col];
                float sc0 = acc[nt][part * 2] * 0.0625f
                          + ((d2.x <= tauf) ? (-d2.x * 0.7071067811865475f) : 1.0f);
                float sc1 = acc[nt][part * 2 + 1] * 0.0625f
                          + ((d2.y <= tauf) ? (-d2.y * 0.7071067811865475f) : 1.0f);
                float cc0 = -__fdividef(20.0f, __expf(2.0f * sc0) + 1.0f);
                float cc1 = -__fdividef(20.0f, __expf(2.0f * sc1) + 1.0f);
                if (anymask) {
                    float2 mk = *(const float2*)&mask[rowoff + col];
                    cc0 += mk.x; cc1 += mk.y;
                }
                const float e0 = __expf(cc0);
                const float e1 = __expf(cc1);
                lsum += e0 + e1;
                *(float2*)&out[rowoff + col] = make_float2(e0, e1);
            }
            atomicAdd(&s_sum[rloc], lsum);
        }
    }
    __syncthreads();

    if (tid < 32) s_sum[tid] = 1.0f / s_sum[tid];
    __syncthreads();

    float2* out2 = (float2*)&out[outbase];
#pragma unroll 4
    for (int i = tid; i < 32 * 256; i += 256) {
        const float inv = s_sum[i >> 8];
        float2 v = out2[i];
        v.x *= inv; v.y *= inv;
        out2[i] = v;
    }
}

// ---------------------------------------------------------------------------
// Launch
// ---------------------------------------------------------------------------
extern "C" void kernel_launch(void* const* d_in, const int* in_sizes, int n_in,
                              void* d_out, int out_size)
{
    const float* enc   = (const float*)d_in[0];
    const float* last  = (const float*)d_in[1];
    const float* load  = (const float*)d_in[2];
    const float* dist  = (const float*)d_in[3];
    const float* mask  = (const float*)d_in[6];
    const float* Wq    = (const float*)d_in[7];
    const float* Wk    = (const float*)d_in[8];
    const float* Wv    = (const float*)d_in[9];
    const float* Wc    = (const float*)d_in[10];
    const float* Wcb   = (const float*)d_in[11];
    float* out = (float*)d_out;

    // pre-split inputs (also resets mask flag)
    cvt_big_kernel<<<dim3(1024, 2), 256>>>(enc, last);
    cvt_w_kernel<<<dim3(64, 4), 256>>>(Wk, Wv, Wc, Wq);

    const size_t smP = (size_t)2 * P_STAGE * sizeof(__nv_bfloat16);
    cudaFuncSetAttribute(proj_kernel,
                         cudaFuncAttributeMaxDynamicSharedMemorySize, (int)smP);
    cudaFuncSetAttribute(proj_q_kernel,
                         cudaFuncAttributeMaxDynamicSharedMemorySize, (int)smP);
    proj_kernel<<<dim3(BB * PP / 128, 4, 2), 256, smP>>>(mask);
    proj_q_kernel<<<dim3(BB * PP / 128, 4), 256, smP>>>(load);

    const size_t smA = (size_t)A6_TOT * sizeof(__nv_bfloat16);
    cudaFuncSetAttribute(attention9_kernel,
                         cudaFuncAttributeMaxDynamicSharedMemorySize, (int)smA);
    dim3 gA(BB * HH, 2);
    attention9_kernel<<<gA, 256, smA>>>(mask);

    cudaFuncSetAttribute(gemm_wc_kernel,
                         cudaFuncAttributeMaxDynamicSharedMemorySize, (int)smP);
    gemm_wc_kernel<<<dim3(BB * PP / 128, 4), 256, smP>>>(Wcb);

    const size_t smF = (size_t)F_TOT * sizeof(__nv_bfloat16);
    cudaFuncSetAttribute(final8_kernel,
                         cudaFuncAttributeMaxDynamicSharedMemorySize, (int)smF);
    dim3 gF(PP / 32, BB);
    final8_kernel<<<gF, 256, smF>>>(dist, mask, out);
}

// round 14
// speedup vs baseline: 1.6304x; 1.6304x over previous
#include <cuda_runtime.h>
#include <cuda_bf16.h>
#include <math.h>

// ---------------------------------------------------------------------------
// Problem constants
// ---------------------------------------------------------------------------
#define BB  32
#define PP  512
#define NN  512
#define EMB 256
#define HH  16
#define DD  16

// Scratch (device globals -- no allocation allowed)
__device__ float g_K[BB * HH * NN * DD];    // [b][h][n][d]
__device__ float g_V[BB * HH * NN * DD];    // [b][h][n][d]
__device__ float g_Q[BB * HH * PP * DD];    // [b][h][p][d]
__device__ float g_att[BB * PP * HH * DD];  // [b][p][h*16+d]
__device__ float g_mh[BB * PP * EMB];       // [b][p][e]
__device__ int   g_mask_nz;                 // 1 if any ninf_mask bit set

// ---------------------------------------------------------------------------
// mma.sync m16n8k16 bf16 + ldmatrix helpers
// ---------------------------------------------------------------------------
__device__ __forceinline__ void mma16816(float* c, const unsigned* a, const unsigned* b) {
    asm volatile(
        "mma.sync.aligned.m16n8k16.row.col.f32.bf16.bf16.f32 "
        "{%0,%1,%2,%3}, {%4,%5,%6,%7}, {%8,%9}, {%0,%1,%2,%3};"
        : "+f"(c[0]), "+f"(c[1]), "+f"(c[2]), "+f"(c[3])
        : "r"(a[0]), "r"(a[1]), "r"(a[2]), "r"(a[3]), "r"(b[0]), "r"(b[1]));
}

__device__ __forceinline__ void ldsm_x4(unsigned& d0, unsigned& d1,
                                        unsigned& d2, unsigned& d3, unsigned addr) {
    asm volatile("ldmatrix.sync.aligned.m8n8.x4.shared.b16 {%0,%1,%2,%3}, [%4];"
                 : "=r"(d0), "=r"(d1), "=r"(d2), "=r"(d3) : "r"(addr));
}

__device__ __forceinline__ unsigned pack_bf16x2(float lo, float hi) {
    unsigned r;
    asm("cvt.rn.satfinite.bf16x2.f32 %0, %1, %2;" : "=r"(r) : "f"(hi), "f"(lo));
    return r;
}

__device__ __forceinline__ void pack_hl(float x0, float x1, unsigned& ph, unsigned& pl) {
    ph = pack_bf16x2(x0, x1);
    const float h0 = __uint_as_float(ph << 16);
    const float h1 = __uint_as_float(ph & 0xFFFF0000u);
    pl = pack_bf16x2(x0 - h0, x1 - h1);
}

__device__ __forceinline__ void cvt_hl(float x, __nv_bfloat16& h, __nv_bfloat16& l) {
    h = __float2bfloat16(x);
    l = __float2bfloat16(x - __bfloat162float(h));
}

__device__ __forceinline__ void store_hl4(__nv_bfloat16* p_h, __nv_bfloat16* p_l, float4 v) {
    unsigned h01, l01, h23, l23;
    pack_hl(v.x, v.y, h01, l01);
    pack_hl(v.z, v.w, h23, l23);
    *(unsigned*)(p_h)     = h01;
    *(unsigned*)(p_h + 2) = h23;
    *(unsigned*)(p_l)     = l01;
    *(unsigned*)(p_l + 2) = l23;
}

#define LDAB 40  // padded bf16 row stride (80 B) -> LDSM conflict-free

// Pipelined GEMM stage layout (elements)
#define P_AH   0
#define P_AL   (128 * LDAB)
#define P_BH   (256 * LDAB)
#define P_BL   (256 * LDAB + 64 * LDAB)
#define P_STAGE (384 * LDAB)   // 15360 elems = 30720 B per stage

// ---------------------------------------------------------------------------
// Flag init
// ---------------------------------------------------------------------------
__global__ void init_flag_kernel() {
    if (threadIdx.x == 0) g_mask_nz = 0;
}

// ---------------------------------------------------------------------------
// Merged projection kernel (pipelined, double-buffered smem).
// blockIdx.z selects K / V / Q; mask OR-scan spread over ALL blocks.
// ---------------------------------------------------------------------------
__global__ __launch_bounds__(256, 2) void proj_kernel(
    const float* __restrict__ enc,
    const float* __restrict__ last,
    const float* __restrict__ loadv,
    const float* __restrict__ Wk,
    const float* __restrict__ Wv,
    const float* __restrict__ Wq,
    const float* __restrict__ mask)
{
    extern __shared__ __nv_bfloat16 smp[];
    __shared__ unsigned sred[8];

    const int z = blockIdx.z;
    const float* Ap = (z == 2) ? last : enc;
    const float* W  = (z == 0) ? Wk : (z == 1) ? Wv : Wq;
    const int ldw   = (z == 2) ? 257 : 256;
    const bool extra = (z == 2);
    float* out = (z == 0) ? g_K : (z == 1) ? g_V : g_Q;

    const int m0 = blockIdx.x * 128;
    const int n0 = blockIdx.y * 64;
    const int tid = threadIdx.x;
    const int warp = tid >> 5, lane = tid & 31;
    const int wm = warp >> 1, wn = warp & 1;
    const int gr = lane >> 2, qc = lane & 3;
    const int lt = lane >> 3, lr = lane & 7;

    // ---- mask OR-scan (spread across all 1536 blocks) ----
    {
        unsigned accm = 0;
        const unsigned bid = blockIdx.z * 512u + blockIdx.y * 128u + blockIdx.x;
        const uint4* m4 = (const uint4*)mask;
        for (unsigned i = bid * 256u + tid; i < 2097152u; i += 1536u * 256u) {
            uint4 v = m4[i];
            accm |= v.x | v.y | v.z | v.w;
        }
#pragma unroll
        for (int o = 16; o; o >>= 1) accm |= __shfl_xor_sync(0xffffffffu, accm, o);
        if (lane == 0) sred[warp] = accm;
        __syncthreads();
        if (tid == 0) {
            unsigned a = 0;
#pragma unroll
            for (int i = 0; i < 8; i++) a |= sred[i];
            if (a) atomicOr(&g_mask_nz, 1);
        }
    }

    const unsigned sb = (unsigned)__cvta_generic_to_shared(smp);
    const unsigned aH0 = sb + (P_AH + (wm * 32 + (lt & 1) * 8 + lr) * LDAB + (lt >> 1) * 8) * 2;
    const unsigned aL0 = sb + (P_AL + (wm * 32 + (lt & 1) * 8 + lr) * LDAB + (lt >> 1) * 8) * 2;
    const unsigned bH0 = sb + (P_BH + (wn * 32 + (lt >> 1) * 8 + lr) * LDAB + (lt & 1) * 8) * 2;
    const unsigned bL0 = sb + (P_BL + (wn * 32 + (lt >> 1) * 8 + lr) * LDAB + (lt & 1) * 8) * 2;

    float acc[2][4][4];
#pragma unroll
    for (int mt = 0; mt < 2; mt++)
#pragma unroll
        for (int nt = 0; nt < 4; nt++)
#pragma unroll
            for (int e = 0; e < 4; e++) acc[mt][nt][e] = 0.0f;

    float4 av[4];
    float wv[2][4];
#pragma unroll
    for (int i = 0; i < 4; i++) {
        const int lin = tid + i * 256;
        const int row = lin >> 3, c4 = lin & 7;
        av[i] = *(const float4*)(Ap + (size_t)(m0 + row) * 256 + c4 * 4);
    }
#pragma unroll
    for (int i = 0; i < 2; i++) {
        const int lin = tid + i * 256;
        const int row = lin >> 3, c4 = lin & 7;
        const float* wp = W + (size_t)(n0 + row) * ldw + c4 * 4;
        if (extra) {
            wv[i][0] = wp[0]; wv[i][1] = wp[1]; wv[i][2] = wp[2]; wv[i][3] = wp[3];
        } else {
            float4 t = *(const float4*)wp;
            wv[i][0] = t.x; wv[i][1] = t.y; wv[i][2] = t.z; wv[i][3] = t.w;
        }
    }

#pragma unroll 1
    for (int kb = 0; kb < 8; kb++) {
        const int bufo = (kb & 1) * P_STAGE;
        __nv_bfloat16* Ah = smp + bufo + P_AH;
        __nv_bfloat16* Al = smp + bufo + P_AL;
        __nv_bfloat16* Bh = smp + bufo + P_BH;
        __nv_bfloat16* Bl = smp + bufo + P_BL;
#pragma unroll
        for (int i = 0; i < 4; i++) {
            const int lin = tid + i * 256;
            const int row = lin >> 3, c4 = lin & 7;
            store_hl4(&Ah[row * LDAB + c4 * 4], &Al[row * LDAB + c4 * 4], av[i]);
        }
#pragma unroll
        for (int i = 0; i < 2; i++) {
            const int lin = tid + i * 256;
            const int row = lin >> 3, c4 = lin & 7;
            float4 t = make_float4(wv[i][0], wv[i][1], wv[i][2], wv[i][3]);
            store_hl4(&Bh[row * LDAB + c4 * 4], &Bl[row * LDAB + c4 * 4], t);
        }
        __syncthreads();

        if (kb < 7) {
            const int k0 = (kb + 1) * 32;
#pragma unroll
            for (int i = 0; i < 4; i++) {
                const int lin = tid + i * 256;
                const int row = lin >> 3, c4 = lin & 7;
                av[i] = *(const float4*)(Ap + (size_t)(m0 + row) * 256 + k0 + c4 * 4);
            }
#pragma unroll
            for (int i = 0; i < 2; i++) {
                const int lin = tid + i * 256;
                const int row = lin >> 3, c4 = lin & 7;
                const float* wp = W + (size_t)(n0 + row) * ldw + k0 + c4 * 4;
                if (extra) {
                    wv[i][0] = wp[0]; wv[i][1] = wp[1]; wv[i][2] = wp[2]; wv[i][3] = wp[3];
                } else {
                    float4 t = *(const float4*)wp;
                    wv[i][0] = t.x; wv[i][1] = t.y; wv[i][2] = t.z; wv[i][3] = t.w;
                }
            }
        }

        const unsigned bo2 = bufo * 2;
#pragma unroll
        for (int ks = 0; ks < 32; ks += 16) {
            unsigned ah[2][4], al[2][4], bh[4][2], bl[4][2];
#pragma unroll
            for (int mt = 0; mt < 2; mt++) {
                ldsm_x4(ah[mt][0], ah[mt][1], ah[mt][2], ah[mt][3],
                        aH0 + bo2 + (mt * 16 * LDAB + ks) * 2);
                ldsm_x4(al[mt][0], al[mt][1], al[mt][2], al[mt][3],
                        aL0 + bo2 + (mt * 16 * LDAB + ks) * 2);
            }
#pragma unroll
            for (int p = 0; p < 2; p++) {
                ldsm_x4(bh[2 * p][0], bh[2 * p][1], bh[2 * p + 1][0], bh[2 * p + 1][1],
                        bH0 + bo2 + (p * 16 * LDAB + ks) * 2);
                ldsm_x4(bl[2 * p][0], bl[2 * p][1], bl[2 * p + 1][0], bl[2 * p + 1][1],
                        bL0 + bo2 + (p * 16 * LDAB + ks) * 2);
            }
#pragma unroll
            for (int mt = 0; mt < 2; mt++)
#pragma unroll
                for (int nt = 0; nt < 4; nt++) {
                    mma16816(acc[mt][nt], ah[mt], bh[nt]);
                    mma16816(acc[mt][nt], ah[mt], bl[nt]);
                    mma16816(acc[mt][nt], al[mt], bh[nt]);
                }
        }
    }

#pragma unroll
    for (int mt = 0; mt < 2; mt++) {
#pragma unroll
        for (int part = 0; part < 2; part++) {
            const int m = m0 + wm * 32 + mt * 16 + gr + part * 8;
            float ex = 0.0f;
            if (extra) ex = loadv[m];
#pragma unroll
            for (int nt = 0; nt < 4; nt++) {
                const int col = n0 + wn * 32 + nt * 8 + 2 * qc;
                float2 v = make_float2(acc[mt][nt][part * 2], acc[mt][nt][part * 2 + 1]);
                if (extra) {
                    v.x += ex * W[(size_t)col * ldw + 256];
                    v.y += ex * W[(size_t)(col + 1) * ldw + 256];
                }
                const int b = m >> 9, n = m & 511;
                const int h = col >> 4, d = col & 15;
                *(float2*)&out[(((size_t)(b * 16 + h) * 512) + n) * 16 + d] = v;
            }
        }
    }
}

// ---------------------------------------------------------------------------
// Wc projection (pipelined, double-buffered): g_att @ Wc^T + bias -> g_mh
// ---------------------------------------------------------------------------
__global__ __launch_bounds__(256, 2) void gemm_wc_kernel(
    const float* __restrict__ W,
    const float* __restrict__ bias)
{
    extern __shared__ __nv_bfloat16 smp[];
    const float* Ap = (const float*)g_att;
    float* out = g_mh;

    const int m0 = blockIdx.x * 128;
    const int n0 = blockIdx.y * 64;
    const int tid = threadIdx.x;
    const int warp = tid >> 5, lane = tid & 31;
    const int wm = warp >> 1, wn = warp & 1;
    const int gr = lane >> 2, qc = lane & 3;
    const int lt = lane >> 3, lr = lane & 7;

    const unsigned sb = (unsigned)__cvta_generic_to_shared(smp);
    const unsigned aH0 = sb + (P_AH + (wm * 32 + (lt & 1) * 8 + lr) * LDAB + (lt >> 1) * 8) * 2;
    const unsigned aL0 = sb + (P_AL + (wm * 32 + (lt & 1) * 8 + lr) * LDAB + (lt >> 1) * 8) * 2;
    const unsigned bH0 = sb + (P_BH + (wn * 32 + (lt >> 1) * 8 + lr) * LDAB + (lt & 1) * 8) * 2;
    const unsigned bL0 = sb + (P_BL + (wn * 32 + (lt >> 1) * 8 + lr) * LDAB + (lt & 1) * 8) * 2;

    float acc[2][4][4];
#pragma unroll
    for (int mt = 0; mt < 2; mt++)
#pragma unroll
        for (int nt = 0; nt < 4; nt++)
#pragma unroll
            for (int e = 0; e < 4; e++) acc[mt][nt][e] = 0.0f;

    float4 av[4], wv[2];
#pragma unroll
    for (int i = 0; i < 4; i++) {
        const int lin = tid + i * 256;
        const int row = lin >> 3, c4 = lin & 7;
        av[i] = *(const float4*)(Ap + (size_t)(m0 + row) * 256 + c4 * 4);
    }
#pragma unroll
    for (int i = 0; i < 2; i++) {
        const int lin = tid + i * 256;
        const int row = lin >> 3, c4 = lin & 7;
        wv[i] = *(const float4*)(W + (size_t)(n0 + row) * 256 + c4 * 4);
    }

#pragma unroll 1
    for (int kb = 0; kb < 8; kb++) {
        const int bufo = (kb & 1) * P_STAGE;
        __nv_bfloat16* Ah = smp + bufo + P_AH;
        __nv_bfloat16* Al = smp + bufo + P_AL;
        __nv_bfloat16* Bh = smp + bufo + P_BH;
        __nv_bfloat16* Bl = smp + bufo + P_BL;
#pragma unroll
        for (int i = 0; i < 4; i++) {
            const int lin = tid + i * 256;
            const int row = lin >> 3, c4 = lin & 7;
            store_hl4(&Ah[row * LDAB + c4 * 4], &Al[row * LDAB + c4 * 4], av[i]);
        }
#pragma unroll
        for (int i = 0; i < 2; i++) {
            const int lin = tid + i * 256;
            const int row = lin >> 3, c4 = lin & 7;
            store_hl4(&Bh[row * LDAB + c4 * 4], &Bl[row * LDAB + c4 * 4], wv[i]);
        }
        __syncthreads();

        if (kb < 7) {
            const int k0 = (kb + 1) * 32;
#pragma unroll
            for (int i = 0; i < 4; i++) {
                const int lin = tid + i * 256;
                const int row = lin >> 3, c4 = lin & 7;
                av[i] = *(const float4*)(Ap + (size_t)(m0 + row) * 256 + k0 + c4 * 4);
            }
#pragma unroll
            for (int i = 0; i < 2; i++) {
                const int lin = tid + i * 256;
                const int row = lin >> 3, c4 = lin & 7;
                wv[i] = *(const float4*)(W + (size_t)(n0 + row) * 256 + k0 + c4 * 4);
            }
        }

        const unsigned bo2 = bufo * 2;
#pragma unroll
        for (int ks = 0; ks < 32; ks += 16) {
            unsigned ah[2][4], al[2][4], bh[4][2], bl[4][2];
#pragma unroll
            for (int mt = 0; mt < 2; mt++) {
                ldsm_x4(ah[mt][0], ah[mt][1], ah[mt][2], ah[mt][3],
                        aH0 + bo2 + (mt * 16 * LDAB + ks) * 2);
                ldsm_x4(al[mt][0], al[mt][1], al[mt][2], al[mt][3],
                        aL0 + bo2 + (mt * 16 * LDAB + ks) * 2);
            }
#pragma unroll
            for (int p = 0; p < 2; p++) {
                ldsm_x4(bh[2 * p][0], bh[2 * p][1], bh[2 * p + 1][0], bh[2 * p + 1][1],
                        bH0 + bo2 + (p * 16 * LDAB + ks) * 2);
                ldsm_x4(bl[2 * p][0], bl[2 * p][1], bl[2 * p + 1][0], bl[2 * p + 1][1],
                        bL0 + bo2 + (p * 16 * LDAB + ks) * 2);
            }
#pragma unroll
            for (int mt = 0; mt < 2; mt++)
#pragma unroll
                for (int nt = 0; nt < 4; nt++) {
                    mma16816(acc[mt][nt], ah[mt], bh[nt]);
                    mma16816(acc[mt][nt], ah[mt], bl[nt]);
                    mma16816(acc[mt][nt], al[mt], bh[nt]);
                }
        }
    }

#pragma unroll
    for (int mt = 0; mt < 2; mt++) {
#pragma unroll
        for (int part = 0; part < 2; part++) {
            const int m = m0 + wm * 32 + mt * 16 + gr + part * 8;
#pragma unroll
            for (int nt = 0; nt < 4; nt++) {
                const int col = n0 + wn * 32 + nt * 8 + 2 * qc;
                float2 v = make_float2(acc[mt][nt][part * 2], acc[mt][nt][part * 2 + 1]);
                v.x += bias[col]; v.y += bias[col + 1];
                *(float2*)&out[(size_t)m * 256 + col] = v;
            }
        }
    }
}

// ---------------------------------------------------------------------------
// Flash attention v8: LDSM + mask-skip + 2 p-tiles per block.
// ---------------------------------------------------------------------------
#define KH_LD 24
#define VT_LD 520
#define A6_KH   0
#define A6_KL   (512 * KH_LD)
#define A6_VTH  (2 * 512 * KH_LD)
#define A6_VTL  (A6_VTH + 16 * VT_LD)
#define A6_QH   (A6_VTL + 16 * VT_LD)
#define A6_QL   (A6_QH + 128 * 16)
#define A6_TOT  (A6_QL + 128 * 16)

__global__ __launch_bounds__(256, 2) void attention8_kernel(
    const float* __restrict__ mask)
{
    extern __shared__ __nv_bfloat16 smb[];
    __nv_bfloat16* Kh  = smb + A6_KH;
    __nv_bfloat16* Kl  = smb + A6_KL;
    __nv_bfloat16* Vth = smb + A6_VTH;
    __nv_bfloat16* Vtl = smb + A6_VTL;
    __nv_bfloat16* Qh  = smb + A6_QH;
    __nv_bfloat16* Ql  = smb + A6_QL;

    const int bh = blockIdx.x;
    const int b  = bh >> 4;
    const int h  = bh & 15;
    const int tid = threadIdx.x;
    const int anymask = g_mask_nz;

    const float4* Kg4 = (const float4*)(g_K + (size_t)bh * (NN * DD));
    for (int i = tid; i < 2048; i += 256) {
        float4 v = Kg4[i];
        const int row = i >> 2, dg = (i & 3) * 4;
        store_hl4(&Kh[row * KH_LD + dg], &Kl[row * KH_LD + dg], v);
    }
    const float4* Vg4 = (const float4*)(g_V + (size_t)bh * (NN * DD));
    for (int i = tid; i < 2048; i += 256) {
        float4 v = Vg4[i];
        const int n = i >> 2, dg = (i & 3) * 4;
        float x[4] = {v.x, v.y, v.z, v.w};
#pragma unroll
        for (int j = 0; j < 4; j++) {
            __nv_bfloat16 hh, ll;
            cvt_hl(x[j], hh, ll);
            Vth[(dg + j) * VT_LD + n] = hh;
            Vtl[(dg + j) * VT_LD + n] = ll;
        }
    }

    const int warp = tid >> 5, lane = tid & 31;
    const int gr = lane >> 2, qc = lane & 3;
    const int lt = lane >> 3, lr = lane & 7;
    const int prow = warp * 16;

    const unsigned sb = (unsigned)__cvta_generic_to_shared(smb);
    const unsigned kBase = sb + ((lt < 2 ? A6_KH : A6_KL)
                                 + lr * KH_LD + (lt & 1) * 8) * 2;
    const unsigned vBase = sb + ((lt < 2 ? A6_VTH : A6_VTL)
                                 + lr * VT_LD + (lt & 1) * 8) * 2;

#pragma unroll 1
    for (int ip = 0; ip < 2; ip++) {
        const int p0 = blockIdx.y * 256 + ip * 128;

        if (ip) __syncthreads();
        const float4* Qg4 = (const float4*)(g_Q + ((size_t)bh * PP + p0) * DD);
        for (int i = tid; i < 512; i += 256) {
            float4 v = Qg4[i];
            v.x *= 0.25f; v.y *= 0.25f; v.z *= 0.25f; v.w *= 0.25f;
            const int row = i >> 2, dg = (i & 3) * 4;
            store_hl4(&Qh[row * 16 + dg], &Ql[row * 16 + dg], v);
        }
        __syncthreads();

        unsigned qh[4], ql[4];
        {
            const int base = (prow + gr) * 16 + 2 * qc;
            qh[0] = *(const unsigned*)&Qh[base];
            qh[1] = *(const unsigned*)&Qh[base + 8 * 16];
            qh[2] = *(const unsigned*)&Qh[base + 8];
            qh[3] = *(const unsigned*)&Qh[base + 8 * 16 + 8];
            ql[0] = *(const unsigned*)&Ql[base];
            ql[1] = *(const unsigned*)&Ql[base + 8 * 16];
            ql[2] = *(const unsigned*)&Ql[base + 8];
            ql[3] = *(const unsigned*)&Ql[base + 8 * 16 + 8];
        }

        float m0 = -1e30f, m1 = -1e30f, l0 = 0.0f, l1 = 0.0f;
        float O[2][4];
#pragma unroll
        for (int nd = 0; nd < 2; nd++)
#pragma unroll
            for (int e = 0; e < 4; e++) O[nd][e] = 0.0f;

        const size_t mrow0 = ((size_t)(b * PP + p0 + prow + gr)) * NN;
        const size_t mrow1 = ((size_t)(b * PP + p0 + prow + gr + 8)) * NN;

#pragma unroll 1
        for (int c = 0; c < 8; c++) {
            const int n0c = c * 64;

            float s[8][4];
#pragma unroll
            for (int nf = 0; nf < 8; nf++) {
                s[nf][0] = s[nf][1] = s[nf][2] = s[nf][3] = 0.0f;
                unsigned kbh[2], kbl[2];
                ldsm_x4(kbh[0], kbh[1], kbl[0], kbl[1],
                        kBase + (n0c + nf * 8) * (KH_LD * 2));
                mma16816(s[nf], qh, kbh);
                mma16816(s[nf], qh, kbl);
                mma16816(s[nf], ql, kbh);
            }

            if (anymask) {
#pragma unroll
                for (int nf = 0; nf < 8; nf++) {
                    const int ncol = n0c + nf * 8 + 2 * qc;
                    float2 mk0 = *(const float2*)&mask[mrow0 + ncol];
                    float2 mk1 = *(const float2*)&mask[mrow1 + ncol];
                    s[nf][0] += mk0.x; s[nf][1] += mk0.y;
                    s[nf][2] += mk1.x; s[nf][3] += mk1.y;
                }
            }

            float mx0 = -1e30f, mx1 = -1e30f;
#pragma unroll
            for (int nf = 0; nf < 8; nf++) {
                mx0 = fmaxf(mx0, fmaxf(s[nf][0], s[nf][1]));
                mx1 = fmaxf(mx1, fmaxf(s[nf][2], s[nf][3]));
            }
            mx0 = fmaxf(mx0, __shfl_xor_sync(0xffffffffu, mx0, 1));
            mx0 = fmaxf(mx0, __shfl_xor_sync(0xffffffffu, mx0, 2));
            mx1 = fmaxf(mx1, __shfl_xor_sync(0xffffffffu, mx1, 1));
            mx1 = fmaxf(mx1, __shfl_xor_sync(0xffffffffu, mx1, 2));

            const float mn0 = fmaxf(m0, mx0);
            const float mn1 = fmaxf(m1, mx1);
            const float f0 = __expf(m0 - mn0);
            const float f1 = __expf(m1 - mn1);
            m0 = mn0; m1 = mn1;
#pragma unroll
            for (int nd = 0; nd < 2; nd++) {
                O[nd][0] *= f0; O[nd][1] *= f0;
                O[nd][2] *= f1; O[nd][3] *= f1;
            }

            float rs0 = 0.0f, rs1 = 0.0f;
#pragma unroll
            for (int nf = 0; nf < 8; nf++) {
                s[nf][0] = __expf(s[nf][0] - mn0);
                s[nf][1] = __expf(s[nf][1] - mn0);
                s[nf][2] = __expf(s[nf][2] - mn1);
                s[nf][3] = __expf(s[nf][3] - mn1);
                rs0 += s[nf][0] + s[nf][1];
                rs1 += s[nf][2] + s[nf][3];
            }
            rs0 += __shfl_xor_sync(0xffffffffu, rs0, 1);
            rs0 += __shfl_xor_sync(0xffffffffu, rs0, 2);
            rs1 += __shfl_xor_sync(0xffffffffu, rs1, 1);
            rs1 += __shfl_xor_sync(0xffffffffu, rs1, 2);
            l0 = l0 * f0 + rs0;
            l1 = l1 * f1 + rs1;

#pragma unroll
            for (int t = 0; t < 4; t++) {
                unsigned ah[4], al[4];
                pack_hl(s[2 * t][0],     s[2 * t][1],     ah[0], al[0]);
                pack_hl(s[2 * t][2],     s[2 * t][3],     ah[1], al[1]);
                pack_hl(s[2 * t + 1][0], s[2 * t + 1][1], ah[2], al[2]);
                pack_hl(s[2 * t + 1][2], s[2 * t + 1][3], ah[3], al[3]);
#pragma unroll
                for (int nd = 0; nd < 2; nd++) {
                    unsigned vbh[2], vbl[2];
                    ldsm_x4(vbh[0], vbh[1], vbl[0], vbl[1],
                            vBase + (nd * 8 * VT_LD + n0c + 16 * t) * 2);
                    mma16816(O[nd], ah, vbh);
                    mma16816(O[nd], ah, vbl);
                    mma16816(O[nd], al, vbh);
                }
            }
        }

        const float inv0 = 1.0f / l0;
        const float inv1 = 1.0f / l1;
        float* op0 = g_att + ((size_t)(b * PP + p0 + prow + gr)) * (HH * DD) + h * DD;
        float* op1 = g_att + ((size_t)(b * PP + p0 + prow + gr + 8)) * (HH * DD) + h * DD;
#pragma unroll
        for (int nd = 0; nd < 2; nd++) {
            *(float2*)&op0[nd * 8 + 2 * qc] = make_float2(O[nd][0] * inv0, O[nd][1] * inv0);
            *(float2*)&op1[nd * 8 + 2 * qc] = make_float2(O[nd][2] * inv1, O[nd][3] * inv1);
        }
    }
}

// ---------------------------------------------------------------------------
// Final fused kernel v7b: tau-first (2-way interleaved search), A staged once,
// B k-pipelined, fixed softmax shift 10, unnormalized exp -> out, rescale.
// ---------------------------------------------------------------------------
#define F_BH 0
#define F_BL (128 * LDAB)
#define F_BSTAGE (256 * LDAB)
#define F_AH (2 * F_BSTAGE)
#define F_A_LD 264
#define F_AL (F_AH + 32 * F_A_LD)
#define F_TOT (F_AL + 32 * F_A_LD)

__global__ __launch_bounds__(256, 2) void final7_kernel(
    const float* __restrict__ enc,
    const float* __restrict__ dist,
    const float* __restrict__ mask,
    float* __restrict__ out)
{
    extern __shared__ __nv_bfloat16 smf[];
    __shared__ float s_tau[32];
    __shared__ float s_sum[32];

    const int b = blockIdx.y;
    const int p0 = blockIdx.x * 32;
    const int tid = threadIdx.x;
    const int warp = tid >> 5, lane = tid & 31;
    const int wm = warp >> 2, wn = warp & 3;
    const int gr = lane >> 2, qc = lane & 3;
    const int lt = lane >> 3, lr = lane & 7;
    const int anymask = g_mask_nz;

    if (tid < 32) s_sum[tid] = 0.0f;

    // ---- phase A: per-row tau, 2 searches interleaved (hides REDUX latency)
#pragma unroll 1
    for (int rp = 0; rp < 2; rp++) {
        const int r0 = warp * 4 + rp * 2;
        unsigned key[2][16];
#pragma unroll
        for (int rr = 0; rr < 2; rr++) {
            const float* drow = dist + ((size_t)(b * PP + p0 + r0 + rr)) * NN;
#pragma unroll
            for (int j = 0; j < 16; j++) {
                unsigned u = __float_as_uint(drow[j * 32 + lane]);
                key[rr][j] = (u & 0x80000000u) ? ~u : (u ^ 0x80000000u);
            }
        }
        unsigned lo[2] = {0u, 0u}, hi[2] = {0xffffffffu, 0xffffffffu};
#pragma unroll 1
        for (int it = 0; it < 32; it++) {
            unsigned mid[2]; int c[2];
#pragma unroll
            for (int rr = 0; rr < 2; rr++) {
                mid[rr] = lo[rr] + ((hi[rr] - lo[rr]) >> 1);
                int cc = 0;
#pragma unroll
                for (int j = 0; j < 16; j++) cc += (key[rr][j] <= mid[rr]) ? 1 : 0;
                c[rr] = cc;
            }
            c[0] = __reduce_add_sync(0xffffffffu, c[0]);
            c[1] = __reduce_add_sync(0xffffffffu, c[1]);
#pragma unroll
            for (int rr = 0; rr < 2; rr++) {
                if (c[rr] >= 100) hi[rr] = mid[rr]; else lo[rr] = mid[rr] + 1;
            }
        }
        if (lane == 0) {
#pragma unroll
            for (int rr = 0; rr < 2; rr++) {
                const unsigned tau = hi[rr];
                const unsigned u = (tau & 0x80000000u) ? (tau ^ 0x80000000u) : ~tau;
                s_tau[r0 + rr] = __uint_as_float(u);
            }
        }
    }

    // ---- stage A (mh tile, FULL K) once ----
    __nv_bfloat16* Ah = smf + F_AH;
    __nv_bfloat16* Al = smf + F_AL;
#pragma unroll
    for (int i = 0; i < 8; i++) {
        const int lin = tid + i * 256;
        const int row = lin >> 6, c4 = lin & 63;
        float4 av = *(const float4*)&g_mh[((size_t)(b * PP + p0 + row)) * 256 + c4 * 4];
        store_hl4(&Ah[row * F_A_LD + c4 * 4], &Al[row * F_A_LD + c4 * 4], av);
    }
    __syncthreads();

    const unsigned sb = (unsigned)__cvta_generic_to_shared(smf);
    const unsigned aHb = sb + (F_AH + (wm * 16 + (lt & 1) * 8 + lr) * F_A_LD + (lt >> 1) * 8) * 2;
    const unsigned aLb = sb + (F_AL + (wm * 16 + (lt & 1) * 8 + lr) * F_A_LD + (lt >> 1) * 8) * 2;
    const unsigned bHb = sb + (F_BH + (wn * 32 + (lt >> 1) * 8 + lr) * LDAB + (lt & 1) * 8) * 2;
    const unsigned bLb = sb + (F_BL + (wn * 32 + (lt >> 1) * 8 + lr) * LDAB + (lt & 1) * 8) * 2;

    const float* encb = enc + (size_t)b * NN * EMB;
    const size_t outbase = ((size_t)(b * PP + p0)) * NN;

#pragma unroll 1
    for (int nc = 0; nc < 4; nc++) {
        float acc[4][4];
#pragma unroll
        for (int nt = 0; nt < 4; nt++)
#pragma unroll
            for (int e = 0; e < 4; e++) acc[nt][e] = 0.0f;

        float4 bv[4];
#pragma unroll
        for (int i = 0; i < 4; i++) {
            const int lin = tid + i * 256;
            const int row = lin >> 3, c4 = lin & 7;
            bv[i] = *(const float4*)&encb[(size_t)(nc * 128 + row) * 256 + c4 * 4];
        }

#pragma unroll 1
        for (int kb = 0; kb < 8; kb++) {
            const int bufo = (kb & 1) * F_BSTAGE;
            __nv_bfloat16* Bh = smf + bufo + F_BH;
            __nv_bfloat16* Bl = smf + bufo + F_BL;
#pragma unroll
            for (int i = 0; i < 4; i++) {
                const int lin = tid + i * 256;
                const int row = lin >> 3, c4 = lin & 7;
                store_hl4(&Bh[row * LDAB + c4 * 4], &Bl[row * LDAB + c4 * 4], bv[i]);
            }
            __syncthreads();

            if (kb < 7) {
                const int k0 = (kb + 1) * 32;
#pragma unroll
                for (int i = 0; i < 4; i++) {
                    const int lin = tid + i * 256;
                    const int row = lin >> 3, c4 = lin & 7;
                    bv[i] = *(const float4*)&encb[(size_t)(nc * 128 + row) * 256 + k0 + c4 * 4];
                }
            }

            const unsigned bo2 = bufo * 2;
#pragma unroll
            for (int ks = 0; ks < 32; ks += 16) {
                const int ka = kb * 32 + ks;
                unsigned ah[4], al[4], bh[4][2], bl[4][2];
                ldsm_x4(ah[0], ah[1], ah[2], ah[3], aHb + ka * 2);
                ldsm_x4(al[0], al[1], al[2], al[3], aLb + ka * 2);
#pragma unroll
                for (int p = 0; p < 2; p++) {
                    ldsm_x4(bh[2 * p][0], bh[2 * p][1], bh[2 * p + 1][0], bh[2 * p + 1][1],
                            bHb + bo2 + (p * 16 * LDAB + ks) * 2);
                    ldsm_x4(bl[2 * p][0], bl[2 * p][1], bl[2 * p + 1][0], bl[2 * p + 1][1],
                            bLb + bo2 + (p * 16 * LDAB + ks) * 2);
                }
#pragma unroll
                for (int nt = 0; nt < 4; nt++) {
                    mma16816(acc[nt], ah, bh[nt]);
                    mma16816(acc[nt], ah, bl[nt]);
                    mma16816(acc[nt], al, bh[nt]);
                }
            }
        }

#pragma unroll
        for (int part = 0; part < 2; part++) {
            const int rloc = wm * 16 + gr + part * 8;
            const float tauf = s_tau[rloc];
            const size_t rowoff = outbase + (size_t)rloc * NN;
            float lsum = 0.0f;
#pragma unroll
            for (int nt = 0; nt < 4; nt++) {
                const int col = nc * 128 + wn * 32 + nt * 8 + 2 * qc;
                float2 d2 = *(const float2*)&dist[rowoff + col];
                float sc0 = acc[nt][part * 2] * 0.0625f
                          + ((d2.x <= tauf) ? (-d2.x * 0.7071067811865475f) : 1.0f);
                float sc1 = acc[nt][part * 2 + 1] * 0.0625f
                          + ((d2.y <= tauf) ? (-d2.y * 0.7071067811865475f) : 1.0f);
                float cc0 = -__fdividef(20.0f, __expf(2.0f * sc0) + 1.0f);
                float cc1 = -__fdividef(20.0f, __expf(2.0f * sc1) + 1.0f);
                if (anymask) {
                    float2 mk = *(const float2*)&mask[rowoff + col];
                    cc0 += mk.x; cc1 += mk.y;
                }
                const float e0 = __expf(cc0);
                const float e1 = __expf(cc1);
                lsum += e0 + e1;
                *(float2*)&out[rowoff + col] = make_float2(e0, e1);
            }
            atomicAdd(&s_sum[rloc], lsum);
        }
    }
    __syncthreads();

    if (tid < 32) s_sum[tid] = 1.0f / s_sum[tid];
    __syncthreads();

    float2* out2 = (float2*)&out[outbase];
#pragma unroll 4
    for (int i = tid; i < 32 * 256; i += 256) {
        const float inv = s_sum[i >> 8];
        float2 v = out2[i];
        v.x *= inv; v.y *= inv;
        out2[i] = v;
    }
}

// ---------------------------------------------------------------------------
// Launch
// ---------------------------------------------------------------------------
extern "C" void kernel_launch(void* const* d_in, const int* in_sizes, int n_in,
                              void* d_out, int out_size)
{
    const float* enc   = (const float*)d_in[0];
    const float* last  = (const float*)d_in[1];
    const float* load  = (const float*)d_in[2];
    const float* dist  = (const float*)d_in[3];
    const float* mask  = (const float*)d_in[6];
    const float* Wq    = (const float*)d_in[7];
    const float* Wk    = (const float*)d_in[8];
    const float* Wv    = (const float*)d_in[9];
    const float* Wc    = (const float*)d_in[10];
    const float* Wcb   = (const float*)d_in[11];
    float* out = (float*)d_out;

    init_flag_kernel<<<1, 32>>>();

    const size_t smP = (size_t)2 * P_STAGE * sizeof(__nv_bfloat16);  // 61440 B
    cudaFuncSetAttribute(proj_kernel,
                         cudaFuncAttributeMaxDynamicSharedMemorySize, (int)smP);
    proj_kernel<<<dim3(BB * PP / 128, 4, 3), 256, smP>>>(
        enc, last, load, Wk, Wv, Wq, mask);

    const size_t smA = (size_t)A6_TOT * sizeof(__nv_bfloat16);  // 90624 B
    cudaFuncSetAttribute(attention8_kernel,
                         cudaFuncAttributeMaxDynamicSharedMemorySize, (int)smA);
    dim3 gA(BB * HH, 2);
    attention8_kernel<<<gA, 256, smA>>>(mask);

    cudaFuncSetAttribute(gemm_wc_kernel,
                         cudaFuncAttributeMaxDynamicSharedMemorySize, (int)smP);
    gemm_wc_kernel<<<dim3(BB * PP / 128, 4), 256, smP>>>(Wc, Wcb);

    const size_t smF = (size_t)F_TOT * sizeof(__nv_bfloat16);  // 74752 B
    cudaFuncSetAttribute(final7_kernel,
                         cudaFuncAttributeMaxDynamicSharedMemorySize, (int)smF);
    dim3 gF(PP / 32, BB);
    final7_kernel<<<gF, 256, smF>>>(enc, dist, mask, out);
}

// round 15
// speedup vs baseline: 1.6826x; 1.0321x over previous
#include <cuda_runtime.h>
#include <cuda_bf16.h>
#include <math.h>

// ---------------------------------------------------------------------------
// Problem constants
// ---------------------------------------------------------------------------
#define BB  32
#define PP  512
#define NN  512
#define EMB 256
#define HH  16
#define DD  16

// Scratch (device globals -- no allocation allowed)
__device__ float g_K[BB * HH * NN * DD];    // [b][h][n][d]
__device__ float g_V[BB * HH * NN * DD];    // [b][h][n][d]
__device__ float g_Q[BB * HH * PP * DD];    // [b][h][p][d]
__device__ float g_att[BB * PP * HH * DD];  // [b][p][h*16+d]
__device__ float g_mh[BB * PP * EMB];       // [b][p][e]
__device__ int   g_mask_nz;                 // 1 if any ninf_mask bit set

// ---------------------------------------------------------------------------
// mma.sync m16n8k16 bf16 + ldmatrix helpers
// ---------------------------------------------------------------------------
__device__ __forceinline__ void mma16816(float* c, const unsigned* a, const unsigned* b) {
    asm volatile(
        "mma.sync.aligned.m16n8k16.row.col.f32.bf16.bf16.f32 "
        "{%0,%1,%2,%3}, {%4,%5,%6,%7}, {%8,%9}, {%0,%1,%2,%3};"
        : "+f"(c[0]), "+f"(c[1]), "+f"(c[2]), "+f"(c[3])
        : "r"(a[0]), "r"(a[1]), "r"(a[2]), "r"(a[3]), "r"(b[0]), "r"(b[1]));
}

__device__ __forceinline__ void ldsm_x4(unsigned& d0, unsigned& d1,
                                        unsigned& d2, unsigned& d3, unsigned addr) {
    asm volatile("ldmatrix.sync.aligned.m8n8.x4.shared.b16 {%0,%1,%2,%3}, [%4];"
                 : "=r"(d0), "=r"(d1), "=r"(d2), "=r"(d3) : "r"(addr));
}

__device__ __forceinline__ unsigned pack_bf16x2(float lo, float hi) {
    unsigned r;
    asm("cvt.rn.satfinite.bf16x2.f32 %0, %1, %2;" : "=r"(r) : "f"(hi), "f"(lo));
    return r;
}

__device__ __forceinline__ void pack_hl(float x0, float x1, unsigned& ph, unsigned& pl) {
    ph = pack_bf16x2(x0, x1);
    const float h0 = __uint_as_float(ph << 16);
    const float h1 = __uint_as_float(ph & 0xFFFF0000u);
    pl = pack_bf16x2(x0 - h0, x1 - h1);
}

__device__ __forceinline__ void cvt_hl(float x, __nv_bfloat16& h, __nv_bfloat16& l) {
    h = __float2bfloat16(x);
    l = __float2bfloat16(x - __bfloat162float(h));
}

__device__ __forceinline__ void store_hl4(__nv_bfloat16* p_h, __nv_bfloat16* p_l, float4 v) {
    unsigned h01, l01, h23, l23;
    pack_hl(v.x, v.y, h01, l01);
    pack_hl(v.z, v.w, h23, l23);
    *(unsigned*)(p_h)     = h01;
    *(unsigned*)(p_h + 2) = h23;
    *(unsigned*)(p_l)     = l01;
    *(unsigned*)(p_l + 2) = l23;
}

#define LDAB 40  // padded bf16 row stride (80 B) -> LDSM conflict-free

// Pipelined GEMM stage layout (elements)
#define P_AH   0
#define P_AL   (128 * LDAB)
#define P_BH   (256 * LDAB)
#define P_BL   (256 * LDAB + 64 * LDAB)
#define P_STAGE (384 * LDAB)   // 15360 elems = 30720 B per stage

// ---------------------------------------------------------------------------
// Flag init
// ---------------------------------------------------------------------------
__global__ void init_flag_kernel() {
    if (threadIdx.x == 0) g_mask_nz = 0;
}

// ---------------------------------------------------------------------------
// Merged projection kernel (pipelined, double-buffered smem).
// blockIdx.z selects K / V / Q; mask OR-scan spread over ALL blocks.
// ---------------------------------------------------------------------------
__global__ __launch_bounds__(256, 2) void proj_kernel(
    const float* __restrict__ enc,
    const float* __restrict__ last,
    const float* __restrict__ loadv,
    const float* __restrict__ Wk,
    const float* __restrict__ Wv,
    const float* __restrict__ Wq,
    const float* __restrict__ mask)
{
    extern __shared__ __nv_bfloat16 smp[];
    __shared__ unsigned sred[8];

    const int z = blockIdx.z;
    const float* Ap = (z == 2) ? last : enc;
    const float* W  = (z == 0) ? Wk : (z == 1) ? Wv : Wq;
    const int ldw   = (z == 2) ? 257 : 256;
    const bool extra = (z == 2);
    float* out = (z == 0) ? g_K : (z == 1) ? g_V : g_Q;

    const int m0 = blockIdx.x * 128;
    const int n0 = blockIdx.y * 64;
    const int tid = threadIdx.x;
    const int warp = tid >> 5, lane = tid & 31;
    const int wm = warp >> 1, wn = warp & 1;
    const int gr = lane >> 2, qc = lane & 3;
    const int lt = lane >> 3, lr = lane & 7;

    // ---- mask OR-scan (spread across all 1536 blocks) ----
    {
        unsigned accm = 0;
        const unsigned bid = blockIdx.z * 512u + blockIdx.y * 128u + blockIdx.x;
        const uint4* m4 = (const uint4*)mask;
        for (unsigned i = bid * 256u + tid; i < 2097152u; i += 1536u * 256u) {
            uint4 v = m4[i];
            accm |= v.x | v.y | v.z | v.w;
        }
#pragma unroll
        for (int o = 16; o; o >>= 1) accm |= __shfl_xor_sync(0xffffffffu, accm, o);
        if (lane == 0) sred[warp] = accm;
        __syncthreads();
        if (tid == 0) {
            unsigned a = 0;
#pragma unroll
            for (int i = 0; i < 8; i++) a |= sred[i];
            if (a) atomicOr(&g_mask_nz, 1);
        }
    }

    const unsigned sb = (unsigned)__cvta_generic_to_shared(smp);
    const unsigned aH0 = sb + (P_AH + (wm * 32 + (lt & 1) * 8 + lr) * LDAB + (lt >> 1) * 8) * 2;
    const unsigned aL0 = sb + (P_AL + (wm * 32 + (lt & 1) * 8 + lr) * LDAB + (lt >> 1) * 8) * 2;
    const unsigned bH0 = sb + (P_BH + (wn * 32 + (lt >> 1) * 8 + lr) * LDAB + (lt & 1) * 8) * 2;
    const unsigned bL0 = sb + (P_BL + (wn * 32 + (lt >> 1) * 8 + lr) * LDAB + (lt & 1) * 8) * 2;

    float acc[2][4][4];
#pragma unroll
    for (int mt = 0; mt < 2; mt++)
#pragma unroll
        for (int nt = 0; nt < 4; nt++)
#pragma unroll
            for (int e = 0; e < 4; e++) acc[mt][nt][e] = 0.0f;

    float4 av[4];
    float wv[2][4];
#pragma unroll
    for (int i = 0; i < 4; i++) {
        const int lin = tid + i * 256;
        const int row = lin >> 3, c4 = lin & 7;
        av[i] = *(const float4*)(Ap + (size_t)(m0 + row) * 256 + c4 * 4);
    }
#pragma unroll
    for (int i = 0; i < 2; i++) {
        const int lin = tid + i * 256;
        const int row = lin >> 3, c4 = lin & 7;
        const float* wp = W + (size_t)(n0 + row) * ldw + c4 * 4;
        if (extra) {
            wv[i][0] = wp[0]; wv[i][1] = wp[1]; wv[i][2] = wp[2]; wv[i][3] = wp[3];
        } else {
            float4 t = *(const float4*)wp;
            wv[i][0] = t.x; wv[i][1] = t.y; wv[i][2] = t.z; wv[i][3] = t.w;
        }
    }

#pragma unroll 1
    for (int kb = 0; kb < 8; kb++) {
        const int bufo = (kb & 1) * P_STAGE;
        __nv_bfloat16* Ah = smp + bufo + P_AH;
        __nv_bfloat16* Al = smp + bufo + P_AL;
        __nv_bfloat16* Bh = smp + bufo + P_BH;
        __nv_bfloat16* Bl = smp + bufo + P_BL;
#pragma unroll
        for (int i = 0; i < 4; i++) {
            const int lin = tid + i * 256;
            const int row = lin >> 3, c4 = lin & 7;
            store_hl4(&Ah[row * LDAB + c4 * 4], &Al[row * LDAB + c4 * 4], av[i]);
        }
#pragma unroll
        for (int i = 0; i < 2; i++) {
            const int lin = tid + i * 256;
            const int row = lin >> 3, c4 = lin & 7;
            float4 t = make_float4(wv[i][0], wv[i][1], wv[i][2], wv[i][3]);
            store_hl4(&Bh[row * LDAB + c4 * 4], &Bl[row * LDAB + c4 * 4], t);
        }
        __syncthreads();

        if (kb < 7) {
            const int k0 = (kb + 1) * 32;
#pragma unroll
            for (int i = 0; i < 4; i++) {
                const int lin = tid + i * 256;
                const int row = lin >> 3, c4 = lin & 7;
                av[i] = *(const float4*)(Ap + (size_t)(m0 + row) * 256 + k0 + c4 * 4);
            }
#pragma unroll
            for (int i = 0; i < 2; i++) {
                const int lin = tid + i * 256;
                const int row = lin >> 3, c4 = lin & 7;
                const float* wp = W + (size_t)(n0 + row) * ldw + k0 + c4 * 4;
                if (extra) {
                    wv[i][0] = wp[0]; wv[i][1] = wp[1]; wv[i][2] = wp[2]; wv[i][3] = wp[3];
                } else {
                    float4 t = *(const float4*)wp;
                    wv[i][0] = t.x; wv[i][1] = t.y; wv[i][2] = t.z; wv[i][3] = t.w;
                }
            }
        }

        const unsigned bo2 = bufo * 2;
#pragma unroll
        for (int ks = 0; ks < 32; ks += 16) {
            unsigned ah[2][4], al[2][4], bh[4][2], bl[4][2];
#pragma unroll
            for (int mt = 0; mt < 2; mt++) {
                ldsm_x4(ah[mt][0], ah[mt][1], ah[mt][2], ah[mt][3],
                        aH0 + bo2 + (mt * 16 * LDAB + ks) * 2);
                ldsm_x4(al[mt][0], al[mt][1], al[mt][2], al[mt][3],
                        aL0 + bo2 + (mt * 16 * LDAB + ks) * 2);
            }
#pragma unroll
            for (int p = 0; p < 2; p++) {
                ldsm_x4(bh[2 * p][0], bh[2 * p][1], bh[2 * p + 1][0], bh[2 * p + 1][1],
                        bH0 + bo2 + (p * 16 * LDAB + ks) * 2);
                ldsm_x4(bl[2 * p][0], bl[2 * p][1], bl[2 * p + 1][0], bl[2 * p + 1][1],
                        bL0 + bo2 + (p * 16 * LDAB + ks) * 2);
            }
#pragma unroll
            for (int mt = 0; mt < 2; mt++)
#pragma unroll
                for (int nt = 0; nt < 4; nt++) {
                    mma16816(acc[mt][nt], ah[mt], bh[nt]);
                    mma16816(acc[mt][nt], ah[mt], bl[nt]);
                    mma16816(acc[mt][nt], al[mt], bh[nt]);
                }
        }
    }

#pragma unroll
    for (int mt = 0; mt < 2; mt++) {
#pragma unroll
        for (int part = 0; part < 2; part++) {
            const int m = m0 + wm * 32 + mt * 16 + gr + part * 8;
            float ex = 0.0f;
            if (extra) ex = loadv[m];
#pragma unroll
            for (int nt = 0; nt < 4; nt++) {
                const int col = n0 + wn * 32 + nt * 8 + 2 * qc;
                float2 v = make_float2(acc[mt][nt][part * 2], acc[mt][nt][part * 2 + 1]);
                if (extra) {
                    v.x += ex * W[(size_t)col * ldw + 256];
                    v.y += ex * W[(size_t)(col + 1) * ldw + 256];
                }
                const int b = m >> 9, n = m & 511;
                const int h = col >> 4, d = col & 15;
                *(float2*)&out[(((size_t)(b * 16 + h) * 512) + n) * 16 + d] = v;
            }
        }
    }
}

// ---------------------------------------------------------------------------
// Wc projection (pipelined, double-buffered): g_att @ Wc^T + bias -> g_mh
// ---------------------------------------------------------------------------
__global__ __launch_bounds__(256, 2) void gemm_wc_kernel(
    const float* __restrict__ W,
    const float* __restrict__ bias)
{
    extern __shared__ __nv_bfloat16 smp[];
    const float* Ap = (const float*)g_att;
    float* out = g_mh;

    const int m0 = blockIdx.x * 128;
    const int n0 = blockIdx.y * 64;
    const int tid = threadIdx.x;
    const int warp = tid >> 5, lane = tid & 31;
    const int wm = warp >> 1, wn = warp & 1;
    const int gr = lane >> 2, qc = lane & 3;
    const int lt = lane >> 3, lr = lane & 7;

    const unsigned sb = (unsigned)__cvta_generic_to_shared(smp);
    const unsigned aH0 = sb + (P_AH + (wm * 32 + (lt & 1) * 8 + lr) * LDAB + (lt >> 1) * 8) * 2;
    const unsigned aL0 = sb + (P_AL + (wm * 32 + (lt & 1) * 8 + lr) * LDAB + (lt >> 1) * 8) * 2;
    const unsigned bH0 = sb + (P_BH + (wn * 32 + (lt >> 1) * 8 + lr) * LDAB + (lt & 1) * 8) * 2;
    const unsigned bL0 = sb + (P_BL + (wn * 32 + (lt >> 1) * 8 + lr) * LDAB + (lt & 1) * 8) * 2;

    float acc[2][4][4];
#pragma unroll
    for (int mt = 0; mt < 2; mt++)
#pragma unroll
        for (int nt = 0; nt < 4; nt++)
#pragma unroll
            for (int e = 0; e < 4; e++) acc[mt][nt][e] = 0.0f;

    float4 av[4], wv[2];
#pragma unroll
    for (int i = 0; i < 4; i++) {
        const int lin = tid + i * 256;
        const int row = lin >> 3, c4 = lin & 7;
        av[i] = *(const float4*)(Ap + (size_t)(m0 + row) * 256 + c4 * 4);
    }
#pragma unroll
    for (int i = 0; i < 2; i++) {
        const int lin = tid + i * 256;
        const int row = lin >> 3, c4 = lin & 7;
        wv[i] = *(const float4*)(W + (size_t)(n0 + row) * 256 + c4 * 4);
    }

#pragma unroll 1
    for (int kb = 0; kb < 8; kb++) {
        const int bufo = (kb & 1) * P_STAGE;
        __nv_bfloat16* Ah = smp + bufo + P_AH;
        __nv_bfloat16* Al = smp + bufo + P_AL;
        __nv_bfloat16* Bh = smp + bufo + P_BH;
        __nv_bfloat16* Bl = smp + bufo + P_BL;
#pragma unroll
        for (int i = 0; i < 4; i++) {
            const int lin = tid + i * 256;
            const int row = lin >> 3, c4 = lin & 7;
            store_hl4(&Ah[row * LDAB + c4 * 4], &Al[row * LDAB + c4 * 4], av[i]);
        }
#pragma unroll
        for (int i = 0; i < 2; i++) {
            const int lin = tid + i * 256;
            const int row = lin >> 3, c4 = lin & 7;
            store_hl4(&Bh[row * LDAB + c4 * 4], &Bl[row * LDAB + c4 * 4], wv[i]);
        }
        __syncthreads();

        if (kb < 7) {
            const int k0 = (kb + 1) * 32;
#pragma unroll
            for (int i = 0; i < 4; i++) {
                const int lin = tid + i * 256;
                const int row = lin >> 3, c4 = lin & 7;
                av[i] = *(const float4*)(Ap + (size_t)(m0 + row) * 256 + k0 + c4 * 4);
            }
#pragma unroll
            for (int i = 0; i < 2; i++) {
                const int lin = tid + i * 256;
                const int row = lin >> 3, c4 = lin & 7;
                wv[i] = *(const float4*)(W + (size_t)(n0 + row) * 256 + k0 + c4 * 4);
            }
        }

        const unsigned bo2 = bufo * 2;
#pragma unroll
        for (int ks = 0; ks < 32; ks += 16) {
            unsigned ah[2][4], al[2][4], bh[4][2], bl[4][2];
#pragma unroll
            for (int mt = 0; mt < 2; mt++) {
                ldsm_x4(ah[mt][0], ah[mt][1], ah[mt][2], ah[mt][3],
                        aH0 + bo2 + (mt * 16 * LDAB + ks) * 2);
                ldsm_x4(al[mt][0], al[mt][1], al[mt][2], al[mt][3],
                        aL0 + bo2 + (mt * 16 * LDAB + ks) * 2);
            }
#pragma unroll
            for (int p = 0; p < 2; p++) {
                ldsm_x4(bh[2 * p][0], bh[2 * p][1], bh[2 * p + 1][0], bh[2 * p + 1][1],
                        bH0 + bo2 + (p * 16 * LDAB + ks) * 2);
                ldsm_x4(bl[2 * p][0], bl[2 * p][1], bl[2 * p + 1][0], bl[2 * p + 1][1],
                        bL0 + bo2 + (p * 16 * LDAB + ks) * 2);
            }
#pragma unroll
            for (int mt = 0; mt < 2; mt++)
#pragma unroll
                for (int nt = 0; nt < 4; nt++) {
                    mma16816(acc[mt][nt], ah[mt], bh[nt]);
                    mma16816(acc[mt][nt], ah[mt], bl[nt]);
                    mma16816(acc[mt][nt], al[mt], bh[nt]);
                }
        }
    }

#pragma unroll
    for (int mt = 0; mt < 2; mt++) {
#pragma unroll
        for (int part = 0; part < 2; part++) {
            const int m = m0 + wm * 32 + mt * 16 + gr + part * 8;
#pragma unroll
            for (int nt = 0; nt < 4; nt++) {
                const int col = n0 + wn * 32 + nt * 8 + 2 * qc;
                float2 v = make_float2(acc[mt][nt][part * 2], acc[mt][nt][part * 2 + 1]);
                v.x += bias[col]; v.y += bias[col + 1];
                *(float2*)&out[(size_t)m * 256 + col] = v;
            }
        }
    }
}

// ---------------------------------------------------------------------------
// Flash attention v10: Q fragments loaded directly from gmem (no Q smem,
// no per-tile barriers). LDSM K/V + mask-skip + 2 p-tiles per block.
// ---------------------------------------------------------------------------
#define KH_LD 24
#define VT_LD 520
#define A6_KH   0
#define A6_KL   (512 * KH_LD)
#define A6_VTH  (2 * 512 * KH_LD)
#define A6_VTL  (A6_VTH + 16 * VT_LD)
#define A6_TOT  (A6_VTL + 16 * VT_LD)   // 41216 elems = 82432 B

__global__ __launch_bounds__(256, 2) void attention10_kernel(
    const float* __restrict__ mask)
{
    extern __shared__ __nv_bfloat16 smb[];
    __nv_bfloat16* Kh  = smb + A6_KH;
    __nv_bfloat16* Kl  = smb + A6_KL;
    __nv_bfloat16* Vth = smb + A6_VTH;
    __nv_bfloat16* Vtl = smb + A6_VTL;

    const int bh = blockIdx.x;
    const int b  = bh >> 4;
    const int h  = bh & 15;
    const int tid = threadIdx.x;
    const int anymask = g_mask_nz;

    // ---- stage K/V once per block ----
    const float4* Kg4 = (const float4*)(g_K + (size_t)bh * (NN * DD));
    for (int i = tid; i < 2048; i += 256) {
        float4 v = Kg4[i];
        const int row = i >> 2, dg = (i & 3) * 4;
        store_hl4(&Kh[row * KH_LD + dg], &Kl[row * KH_LD + dg], v);
    }
    const float4* Vg4 = (const float4*)(g_V + (size_t)bh * (NN * DD));
    for (int i = tid; i < 2048; i += 256) {
        float4 v = Vg4[i];
        const int n = i >> 2, dg = (i & 3) * 4;
        float x[4] = {v.x, v.y, v.z, v.w};
#pragma unroll
        for (int j = 0; j < 4; j++) {
            __nv_bfloat16 hh, ll;
            cvt_hl(x[j], hh, ll);
            Vth[(dg + j) * VT_LD + n] = hh;
            Vtl[(dg + j) * VT_LD + n] = ll;
        }
    }
    __syncthreads();

    const int warp = tid >> 5, lane = tid & 31;
    const int gr = lane >> 2, qc = lane & 3;
    const int lt = lane >> 3, lr = lane & 7;
    const int prow = warp * 16;

    const unsigned sb = (unsigned)__cvta_generic_to_shared(smb);
    const unsigned kBase = sb + ((lt < 2 ? A6_KH : A6_KL)
                                 + lr * KH_LD + (lt & 1) * 8) * 2;
    const unsigned vBase = sb + ((lt < 2 ? A6_VTH : A6_VTL)
                                 + lr * VT_LD + (lt & 1) * 8) * 2;

#pragma unroll 1
    for (int ip = 0; ip < 2; ip++) {
        const int p0 = blockIdx.y * 256 + ip * 128;

        // ---- Q fragments: direct gmem loads (rows prow+gr, prow+gr+8) ----
        unsigned qh[4], ql[4];
        {
            const float2* q0 = (const float2*)(g_Q + ((size_t)bh * PP + p0 + prow + gr) * DD);
            const float2* q1 = (const float2*)(g_Q + ((size_t)bh * PP + p0 + prow + gr + 8) * DD);
            float2 a = q0[qc], bq = q1[qc], cq = q0[qc + 4], d = q1[qc + 4];
            pack_hl(a.x * 0.25f,  a.y * 0.25f,  qh[0], ql[0]);
            pack_hl(bq.x * 0.25f, bq.y * 0.25f, qh[1], ql[1]);
            pack_hl(cq.x * 0.25f, cq.y * 0.25f, qh[2], ql[2]);
            pack_hl(d.x * 0.25f,  d.y * 0.25f,  qh[3], ql[3]);
        }

        float m0 = -1e30f, m1 = -1e30f, l0 = 0.0f, l1 = 0.0f;
        float O[2][4];
#pragma unroll
        for (int nd = 0; nd < 2; nd++)
#pragma unroll
            for (int e = 0; e < 4; e++) O[nd][e] = 0.0f;

        const size_t mrow0 = ((size_t)(b * PP + p0 + prow + gr)) * NN;
        const size_t mrow1 = ((size_t)(b * PP + p0 + prow + gr + 8)) * NN;

#pragma unroll 1
        for (int c = 0; c < 8; c++) {
            const int n0c = c * 64;

            float s[8][4];
#pragma unroll
            for (int nf = 0; nf < 8; nf++) {
                s[nf][0] = s[nf][1] = s[nf][2] = s[nf][3] = 0.0f;
                unsigned kbh[2], kbl[2];
                ldsm_x4(kbh[0], kbh[1], kbl[0], kbl[1],
                        kBase + (n0c + nf * 8) * (KH_LD * 2));
                mma16816(s[nf], qh, kbh);
                mma16816(s[nf], qh, kbl);
                mma16816(s[nf], ql, kbh);
            }

            if (anymask) {
#pragma unroll
                for (int nf = 0; nf < 8; nf++) {
                    const int ncol = n0c + nf * 8 + 2 * qc;
                    float2 mk0 = *(const float2*)&mask[mrow0 + ncol];
                    float2 mk1 = *(const float2*)&mask[mrow1 + ncol];
                    s[nf][0] += mk0.x; s[nf][1] += mk0.y;
                    s[nf][2] += mk1.x; s[nf][3] += mk1.y;
                }
            }

            float mx0 = -1e30f, mx1 = -1e30f;
#pragma unroll
            for (int nf = 0; nf < 8; nf++) {
                mx0 = fmaxf(mx0, fmaxf(s[nf][0], s[nf][1]));
                mx1 = fmaxf(mx1, fmaxf(s[nf][2], s[nf][3]));
            }
            mx0 = fmaxf(mx0, __shfl_xor_sync(0xffffffffu, mx0, 1));
            mx0 = fmaxf(mx0, __shfl_xor_sync(0xffffffffu, mx0, 2));
            mx1 = fmaxf(mx1, __shfl_xor_sync(0xffffffffu, mx1, 1));
            mx1 = fmaxf(mx1, __shfl_xor_sync(0xffffffffu, mx1, 2));

            const float mn0 = fmaxf(m0, mx0);
            const float mn1 = fmaxf(m1, mx1);
            const float f0 = __expf(m0 - mn0);
            const float f1 = __expf(m1 - mn1);
            m0 = mn0; m1 = mn1;
#pragma unroll
            for (int nd = 0; nd < 2; nd++) {
                O[nd][0] *= f0; O[nd][1] *= f0;
                O[nd][2] *= f1; O[nd][3] *= f1;
            }

            float rs0 = 0.0f, rs1 = 0.0f;
#pragma unroll
            for (int nf = 0; nf < 8; nf++) {
                s[nf][0] = __expf(s[nf][0] - mn0);
                s[nf][1] = __expf(s[nf][1] - mn0);
                s[nf][2] = __expf(s[nf][2] - mn1);
                s[nf][3] = __expf(s[nf][3] - mn1);
                rs0 += s[nf][0] + s[nf][1];
                rs1 += s[nf][2] + s[nf][3];
            }
            rs0 += __shfl_xor_sync(0xffffffffu, rs0, 1);
            rs0 += __shfl_xor_sync(0xffffffffu, rs0, 2);
            rs1 += __shfl_xor_sync(0xffffffffu, rs1, 1);
            rs1 += __shfl_xor_sync(0xffffffffu, rs1, 2);
            l0 = l0 * f0 + rs0;
            l1 = l1 * f1 + rs1;

#pragma unroll
            for (int t = 0; t < 4; t++) {
                unsigned ah[4], al[4];
                pack_hl(s[2 * t][0],     s[2 * t][1],     ah[0], al[0]);
                pack_hl(s[2 * t][2],     s[2 * t][3],     ah[1], al[1]);
                pack_hl(s[2 * t + 1][0], s[2 * t + 1][1], ah[2], al[2]);
                pack_hl(s[2 * t + 1][2], s[2 * t + 1][3], ah[3], al[3]);
#pragma unroll
                for (int nd = 0; nd < 2; nd++) {
                    unsigned vbh[2], vbl[2];
                    ldsm_x4(vbh[0], vbh[1], vbl[0], vbl[1],
                            vBase + (nd * 8 * VT_LD + n0c + 16 * t) * 2);
                    mma16816(O[nd], ah, vbh);
                    mma16816(O[nd], ah, vbl);
                    mma16816(O[nd], al, vbh);
                }
            }
        }

        const float inv0 = 1.0f / l0;
        const float inv1 = 1.0f / l1;
        float* op0 = g_att + ((size_t)(b * PP + p0 + prow + gr)) * (HH * DD) + h * DD;
        float* op1 = g_att + ((size_t)(b * PP + p0 + prow + gr + 8)) * (HH * DD) + h * DD;
#pragma unroll
        for (int nd = 0; nd < 2; nd++) {
            *(float2*)&op0[nd * 8 + 2 * qc] = make_float2(O[nd][0] * inv0, O[nd][1] * inv0);
            *(float2*)&op1[nd * 8 + 2 * qc] = make_float2(O[nd][2] * inv1, O[nd][3] * inv1);
        }
    }
}

// ---------------------------------------------------------------------------
// Final fused kernel v7b: tau-first (2-way interleaved search), A staged once,
// B k-pipelined, fixed softmax shift 10, unnormalized exp -> out, rescale.
// ---------------------------------------------------------------------------
#define F_BH 0
#define F_BL (128 * LDAB)
#define F_BSTAGE (256 * LDAB)
#define F_AH (2 * F_BSTAGE)
#define F_A_LD 264
#define F_AL (F_AH + 32 * F_A_LD)
#define F_TOT (F_AL + 32 * F_A_LD)

__global__ __launch_bounds__(256, 2) void final7_kernel(
    const float* __restrict__ enc,
    const float* __restrict__ dist,
    const float* __restrict__ mask,
    float* __restrict__ out)
{
    extern __shared__ __nv_bfloat16 smf[];
    __shared__ float s_tau[32];
    __shared__ float s_sum[32];

    const int b = blockIdx.y;
    const int p0 = blockIdx.x * 32;
    const int tid = threadIdx.x;
    const int warp = tid >> 5, lane = tid & 31;
    const int wm = warp >> 2, wn = warp & 3;
    const int gr = lane >> 2, qc = lane & 3;
    const int lt = lane >> 3, lr = lane & 7;
    const int anymask = g_mask_nz;

    if (tid < 32) s_sum[tid] = 0.0f;

    // ---- phase A: per-row tau, 2 searches interleaved ----
#pragma unroll 1
    for (int rp = 0; rp < 2; rp++) {
        const int r0 = warp * 4 + rp * 2;
        unsigned key[2][16];
#pragma unroll
        for (int rr = 0; rr < 2; rr++) {
            const float* drow = dist + ((size_t)(b * PP + p0 + r0 + rr)) * NN;
#pragma unroll
            for (int j = 0; j < 16; j++) {
                unsigned u = __float_as_uint(drow[j * 32 + lane]);
                key[rr][j] = (u & 0x80000000u) ? ~u : (u ^ 0x80000000u);
            }
        }
        unsigned lo[2] = {0u, 0u}, hi[2] = {0xffffffffu, 0xffffffffu};
#pragma unroll 1
        for (int it = 0; it < 32; it++) {
            unsigned mid[2]; int c[2];
#pragma unroll
            for (int rr = 0; rr < 2; rr++) {
                mid[rr] = lo[rr] + ((hi[rr] - lo[rr]) >> 1);
                int cc = 0;
#pragma unroll
                for (int j = 0; j < 16; j++) cc += (key[rr][j] <= mid[rr]) ? 1 : 0;
                c[rr] = cc;
            }
            c[0] = __reduce_add_sync(0xffffffffu, c[0]);
            c[1] = __reduce_add_sync(0xffffffffu, c[1]);
#pragma unroll
            for (int rr = 0; rr < 2; rr++) {
                if (c[rr] >= 100) hi[rr] = mid[rr]; else lo[rr] = mid[rr] + 1;
            }
        }
        if (lane == 0) {
#pragma unroll
            for (int rr = 0; rr < 2; rr++) {
                const unsigned tau = hi[rr];
                const unsigned u = (tau & 0x80000000u) ? (tau ^ 0x80000000u) : ~tau;
                s_tau[r0 + rr] = __uint_as_float(u);
            }
        }
    }

    // ---- stage A (mh tile, FULL K) once ----
    __nv_bfloat16* Ah = smf + F_AH;
    __nv_bfloat16* Al = smf + F_AL;
#pragma unroll
    for (int i = 0; i < 8; i++) {
        const int lin = tid + i * 256;
        const int row = lin >> 6, c4 = lin & 63;
        float4 av = *(const float4*)&g_mh[((size_t)(b * PP + p0 + row)) * 256 + c4 * 4];
        store_hl4(&Ah[row * F_A_LD + c4 * 4], &Al[row * F_A_LD + c4 * 4], av);
    }
    __syncthreads();

    const unsigned sb = (unsigned)__cvta_generic_to_shared(smf);
    const unsigned aHb = sb + (F_AH + (wm * 16 + (lt & 1) * 8 + lr) * F_A_LD + (lt >> 1) * 8) * 2;
    const unsigned aLb = sb + (F_AL + (wm * 16 + (lt & 1) * 8 + lr) * F_A_LD + (lt >> 1) * 8) * 2;
    const unsigned bHb = sb + (F_BH + (wn * 32 + (lt >> 1) * 8 + lr) * LDAB + (lt & 1) * 8) * 2;
    const unsigned bLb = sb + (F_BL + (wn * 32 + (lt >> 1) * 8 + lr) * LDAB + (lt & 1) * 8) * 2;

    const float* encb = enc + (size_t)b * NN * EMB;
    const size_t outbase = ((size_t)(b * PP + p0)) * NN;

#pragma unroll 1
    for (int nc = 0; nc < 4; nc++) {
        float acc[4][4];
#pragma unroll
        for (int nt = 0; nt < 4; nt++)
#pragma unroll
            for (int e = 0; e < 4; e++) acc[nt][e] = 0.0f;

        float4 bv[4];
#pragma unroll
        for (int i = 0; i < 4; i++) {
            const int lin = tid + i * 256;
            const int row = lin >> 3, c4 = lin & 7;
            bv[i] = *(const float4*)&encb[(size_t)(nc * 128 + row) * 256 + c4 * 4];
        }

#pragma unroll 1
        for (int kb = 0; kb < 8; kb++) {
            const int bufo = (kb & 1) * F_BSTAGE;
            __nv_bfloat16* Bh = smf + bufo + F_BH;
            __nv_bfloat16* Bl = smf + bufo + F_BL;
#pragma unroll
            for (int i = 0; i < 4; i++) {
                const int lin = tid + i * 256;
                const int row = lin >> 3, c4 = lin & 7;
                store_hl4(&Bh[row * LDAB + c4 * 4], &Bl[row * LDAB + c4 * 4], bv[i]);
            }
            __syncthreads();

            if (kb < 7) {
                const int k0 = (kb + 1) * 32;
#pragma unroll
                for (int i = 0; i < 4; i++) {
                    const int lin = tid + i * 256;
                    const int row = lin >> 3, c4 = lin & 7;
                    bv[i] = *(const float4*)&encb[(size_t)(nc * 128 + row) * 256 + k0 + c4 * 4];
                }
            }

            const unsigned bo2 = bufo * 2;
#pragma unroll
            for (int ks = 0; ks < 32; ks += 16) {
                const int ka = kb * 32 + ks;
                unsigned ah[4], al[4], bh[4][2], bl[4][2];
                ldsm_x4(ah[0], ah[1], ah[2], ah[3], aHb + ka * 2);
                ldsm_x4(al[0], al[1], al[2], al[3], aLb + ka * 2);
#pragma unroll
                for (int p = 0; p < 2; p++) {
                    ldsm_x4(bh[2 * p][0], bh[2 * p][1], bh[2 * p + 1][0], bh[2 * p + 1][1],
                            bHb + bo2 + (p * 16 * LDAB + ks) * 2);
                    ldsm_x4(bl[2 * p][0], bl[2 * p][1], bl[2 * p + 1][0], bl[2 * p + 1][1],
                            bLb + bo2 + (p * 16 * LDAB + ks) * 2);
                }
#pragma unroll
                for (int nt = 0; nt < 4; nt++) {
                    mma16816(acc[nt], ah, bh[nt]);
                    mma16816(acc[nt], ah, bl[nt]);
                    mma16816(acc[nt], al, bh[nt]);
                }
            }
        }

#pragma unroll
        for (int part = 0; part < 2; part++) {
            const int rloc = wm * 16 + gr + part * 8;
            const float tauf = s_tau[rloc];
            const size_t rowoff = outbase + (size_t)rloc * NN;
            float lsum = 0.0f;
#pragma unroll
            for (int nt = 0; nt < 4; nt++) {
                const int col = nc * 128 + wn * 32 + nt * 8 + 2 * qc;
                float2 d2 = *(const float2*)&dist[rowoff + col];
                float sc0 = acc[nt][part * 2] * 0.0625f
                          + ((d2.x <= tauf) ? (-d2.x * 0.7071067811865475f) : 1.0f);
                float sc1 = acc[nt][part * 2 + 1] * 0.0625f
                          + ((d2.y <= tauf) ? (-d2.y * 0.7071067811865475f) : 1.0f);
                float cc0 = -__fdividef(20.0f, __expf(2.0f * sc0) + 1.0f);
                float cc1 = -__fdividef(20.0f, __expf(2.0f * sc1) + 1.0f);
                if (anymask) {
                    float2 mk = *(const float2*)&mask[rowoff + col];
                    cc0 += mk.x; cc1 += mk.y;
                }
                const float e0 = __expf(cc0);
                const float e1 = __expf(cc1);
                lsum += e0 + e1;
                *(float2*)&out[rowoff + col] = make_float2(e0, e1);
            }
            atomicAdd(&s_sum[rloc], lsum);
        }
    }
    __syncthreads();

    if (tid < 32) s_sum[tid] = 1.0f / s_sum[tid];
    __syncthreads();

    float2* out2 = (float2*)&out[outbase];
#pragma unroll 4
    for (int i = tid; i < 32 * 256; i += 256) {
        const float inv = s_sum[i >> 8];
        float2 v = out2[i];
        v.x *= inv; v.y *= inv;
        out2[i] = v;
    }
}

// ---------------------------------------------------------------------------
// Launch
// ---------------------------------------------------------------------------
extern "C" void kernel_launch(void* const* d_in, const int* in_sizes, int n_in,
                              void* d_out, int out_size)
{
    const float* enc   = (const float*)d_in[0];
    const float* last  = (const float*)d_in[1];
    const float* load  = (const float*)d_in[2];
    const float* dist  = (const float*)d_in[3];
    const float* mask  = (const float*)d_in[6];
    const float* Wq    = (const float*)d_in[7];
    const float* Wk    = (const float*)d_in[8];
    const float* Wv    = (const float*)d_in[9];
    const float* Wc    = (const float*)d_in[10];
    const float* Wcb   = (const float*)d_in[11];
    float* out = (float*)d_out;

    init_flag_kernel<<<1, 32>>>();

    const size_t smP = (size_t)2 * P_STAGE * sizeof(__nv_bfloat16);  // 61440 B
    cudaFuncSetAttribute(proj_kernel,
                         cudaFuncAttributeMaxDynamicSharedMemorySize, (int)smP);
    proj_kernel<<<dim3(BB * PP / 128, 4, 3), 256, smP>>>(
        enc, last, load, Wk, Wv, Wq, mask);

    const size_t smA = (size_t)A6_TOT * sizeof(__nv_bfloat16);  // 82432 B
    cudaFuncSetAttribute(attention10_kernel,
                         cudaFuncAttributeMaxDynamicSharedMemorySize, (int)smA);
    dim3 gA(BB * HH, 2);
    attention10_kernel<<<gA, 256, smA>>>(mask);

    cudaFuncSetAttribute(gemm_wc_kernel,
                         cudaFuncAttributeMaxDynamicSharedMemorySize, (int)smP);
    gemm_wc_kernel<<<dim3(BB * PP / 128, 4), 256, smP>>>(Wc, Wcb);

    const size_t smF = (size_t)F_TOT * sizeof(__nv_bfloat16);  // 74752 B
    cudaFuncSetAttribute(final7_kernel,
                         cudaFuncAttributeMaxDynamicSharedMemorySize, (int)smF);
    dim3 gF(PP / 32, BB);
    final7_kernel<<<gF, 256, smF>>>(enc, dist, mask, out);
}